// round 7
// baseline (speedup 1.0000x reference)
#include <cuda_runtime.h>
#include <cuda_bf16.h>
#include <cstdint>

#define HDIM 1024
#define SDIM 2048
#define VDIM 50257
#define NBOUND 25
#define MERGED 2048
#define NBLK 296           // 148 SMs x 2 co-resident blocks
#define NTHR 512
#define NVB 264            // blocks doing vocab h-half in phase 1
#define NCH 32             // chain blocks (264..295)
#define NWTOT (NBLK * 16)  // 4736 warps
#define NW1 (NVB * 16)     // 4224 phase-1 vocab warps

// ---------------- device scratch ----------------
__device__ __align__(16) float g_h[2][HDIM];
__device__ __align__(16) float g_q[HDIM];
__device__ __align__(16) float g_s[SDIM];
__device__ __align__(16) float g_ctx_part[8][HDIM];
__device__ __align__(16) float g_eproj[(size_t)SDIM * HDIM];          // 8 MB
__device__ __align__(16) __nv_bfloat16 g_wbf[(size_t)VDIM * MERGED];  // 206 MB split-half
__device__ __align__(16) float g_ub[VDIM];
__device__ __align__(16) float g_partA[VDIM];
__device__ __align__(16) float g_partB[VDIM];
__device__ unsigned g_M[2];
__device__ unsigned long long g_best[2];
__device__ unsigned g_bar_count, g_bar_phase;
__device__ unsigned g_sub_count, g_sub_phase;

// ---------------- helpers ----------------
__device__ __forceinline__ float warp_sum(float v) {
#pragma unroll
    for (int o = 16; o; o >>= 1) v += __shfl_xor_sync(0xffffffffu, v, o);
    return v;
}
__device__ __forceinline__ unsigned enc_f(float f) {
    unsigned b = __float_as_uint(f);
    return (b & 0x80000000u) ? ~b : (b | 0x80000000u);
}
__device__ __forceinline__ float dec_f(unsigned u) {
    unsigned b = (u & 0x80000000u) ? (u ^ 0x80000000u) : ~u;
    return __uint_as_float(b);
}
__device__ __forceinline__ float exp2_fast(float y) {
    y = fminf(fmaxf(y, -60.f), 60.f);
    float n = rintf(y);
    float f = y - n;
    float p = 1.5403530e-4f;
    p = fmaf(p, f, 1.3333558e-3f);
    p = fmaf(p, f, 9.6181291e-3f);
    p = fmaf(p, f, 5.5504109e-2f);
    p = fmaf(p, f, 2.4022651e-1f);
    p = fmaf(p, f, 6.9314718e-1f);
    p = fmaf(p, f, 1.0f);
    return __int_as_float(((int)n + 127) << 23) * p;
}
__device__ __forceinline__ float tanh_fast(float x) {
    float e = exp2_fast(x * 2.885390081777927f);
    return 1.f - 2.f / (e + 1.f);
}
__device__ __forceinline__ float sigmoid_fast(float x) {
    float e = exp2_fast(-1.4426950408889634f * x);
    return 1.f / (1.f + e);
}

// grid-wide barrier (all NBLK blocks)
__device__ __forceinline__ void gsync(unsigned& tgt) {
    __syncthreads();
    if (threadIdx.x == 0) {
        __threadfence();
        unsigned v = atomicAdd(&g_bar_count, 1u);
        if (v == NBLK - 1) {
            g_bar_count = 0;
            asm volatile("st.release.gpu.u32 [%0], %1;" :: "l"(&g_bar_phase), "r"(tgt) : "memory");
        } else {
            unsigned p;
            do {
                asm volatile("ld.acquire.gpu.u32 %0, [%1];" : "=r"(p) : "l"(&g_bar_phase) : "memory");
            } while ((int)(p - tgt) < 0);
        }
    }
    __syncthreads();
    tgt++;
}

// sub-barrier among the NCH chain blocks only
__device__ __forceinline__ void subsync(unsigned& stgt) {
    __syncthreads();
    if (threadIdx.x == 0) {
        __threadfence();
        unsigned v = atomicAdd(&g_sub_count, 1u);
        if (v == NCH - 1) {
            g_sub_count = 0;
            asm volatile("st.release.gpu.u32 [%0], %1;" :: "l"(&g_sub_phase), "r"(stgt) : "memory");
        } else {
            unsigned p;
            do {
                asm volatile("ld.acquire.gpu.u32 %0, [%1];" : "=r"(p) : "l"(&g_sub_phase) : "memory");
            } while ((int)(p - stgt) < 0);
        }
    }
    __syncthreads();
    stgt++;
}

// ---------------- the persistent mega-kernel ----------------
__global__ __launch_bounds__(NTHR, 2) void k_mega(
    const float* __restrict__ hidden, const float* __restrict__ emb,
    const float* __restrict__ emb_table,
    const float* __restrict__ W_ih, const float* __restrict__ W_hh,
    const float* __restrict__ b_ih, const float* __restrict__ b_hh,
    const float* __restrict__ We, const float* __restrict__ Wq,
    const float* __restrict__ ba, const float* __restrict__ va,
    const float* __restrict__ Wout, const float* __restrict__ bout,
    float* __restrict__ out)
{
    __shared__ __align__(16) float s_As[128 * 36];   // eproj A tile; reused as merge vec
    __shared__ __align__(16) float s_Bs[64 * 33];    // eproj B tile; reused as chain w-stage
    __shared__ float s_gru[4][4][6];
    __shared__ float s_red[16];
    __shared__ float s_sm[2];
    __shared__ int s_cand[32];
    __shared__ int s_cnt;
    __shared__ int s_word;

    const int tid = threadIdx.x;
    const int blk = blockIdx.x;
    const int w = tid >> 5, lane = tid & 31;

    unsigned tgt  = *((volatile unsigned*)&g_bar_phase) + 1;
    unsigned stgt = *((volatile unsigned*)&g_sub_phase) + 1;

    // ---------- phase 0: init + (eproj || quant) concurrent ----------
    if (blk == 0 && tid < 2) { g_M[tid] = 0u; g_best[tid] = 0ull; }
    if (blk == 1) {
        for (int i = tid; i < HDIM; i += NTHR) g_h[0][i] = hidden[i];
    }

    if (blk < 256) {
        // eproj: one 128x64 tile per block
        const int ts0 = (blk >> 4) * 128;
        const int ta0 = (blk & 15) * 64;
        const int ts = tid >> 4;
        const int ta = tid & 15;
        float acc[4][4];
#pragma unroll
        for (int i = 0; i < 4; i++)
#pragma unroll
            for (int j = 0; j < 4; j++) acc[i][j] = 0.f;
        for (int kt = 0; kt < 1024; kt += 32) {
#pragma unroll
            for (int r = 0; r < 8; r++) {
                int e0 = tid + NTHR * r;
                int si = e0 >> 5, kk = e0 & 31;
                s_As[si * 36 + kk] = emb[(size_t)(ts0 + si) * 1024 + kt + kk];
            }
#pragma unroll
            for (int r = 0; r < 4; r++) {
                int e0 = tid + NTHR * r;
                int ai = e0 >> 5, kk = e0 & 31;
                s_Bs[ai * 33 + kk] = We[(size_t)(ta0 + ai) * 1024 + kt + kk];
            }
            __syncthreads();
#pragma unroll
            for (int k = 0; k < 32; k++) {
                float a0 = s_As[ts * 36 + k];
                float a1 = s_As[(ts + 32) * 36 + k];
                float a2 = s_As[(ts + 64) * 36 + k];
                float a3 = s_As[(ts + 96) * 36 + k];
                float b0 = s_Bs[(ta * 4 + 0) * 33 + k];
                float b1 = s_Bs[(ta * 4 + 1) * 33 + k];
                float b2 = s_Bs[(ta * 4 + 2) * 33 + k];
                float b3 = s_Bs[(ta * 4 + 3) * 33 + k];
                acc[0][0] = fmaf(a0, b0, acc[0][0]); acc[0][1] = fmaf(a0, b1, acc[0][1]);
                acc[0][2] = fmaf(a0, b2, acc[0][2]); acc[0][3] = fmaf(a0, b3, acc[0][3]);
                acc[1][0] = fmaf(a1, b0, acc[1][0]); acc[1][1] = fmaf(a1, b1, acc[1][1]);
                acc[1][2] = fmaf(a1, b2, acc[1][2]); acc[1][3] = fmaf(a1, b3, acc[1][3]);
                acc[2][0] = fmaf(a2, b0, acc[2][0]); acc[2][1] = fmaf(a2, b1, acc[2][1]);
                acc[2][2] = fmaf(a2, b2, acc[2][2]); acc[2][3] = fmaf(a2, b3, acc[2][3]);
                acc[3][0] = fmaf(a3, b0, acc[3][0]); acc[3][1] = fmaf(a3, b1, acc[3][1]);
                acc[3][2] = fmaf(a3, b2, acc[3][2]); acc[3][3] = fmaf(a3, b3, acc[3][3]);
            }
            __syncthreads();
        }
        float4 bb = __ldg((const float4*)(ba + ta0) + ta);
#pragma unroll
        for (int i = 0; i < 4; i++) {
            float4 o = make_float4(acc[i][0] + bb.x, acc[i][1] + bb.y,
                                   acc[i][2] + bb.z, acc[i][3] + bb.w);
            *(float4*)&g_eproj[(size_t)(ts0 + ts + 32 * i) * 1024 + ta0 + ta * 4] = o;
        }
    } else {
        // quant (40 blocks), 2 uint4 outputs per iteration, SPLIT-HALF layout
        const size_t np = (size_t)VDIM * MERGED / 16;      // pairs of uint4 outputs
        const size_t CTXOFF4 = (size_t)VDIM * 128;
        for (size_t ip = (size_t)(blk - 256) * NTHR + tid; ip < np;
             ip += (size_t)40 * NTHR) {
            size_t o0 = ip * 2;
            const float4* p = (const float4*)Wout + o0 * 2;
            float4 a0 = __ldcs(p), b0 = __ldcs(p + 1);
            float4 a1 = __ldcs(p + 2), b1 = __ldcs(p + 3);
            uint4 u0, u1;
            *(__nv_bfloat162*)&u0.x = __nv_bfloat162(__float2bfloat16(a0.x), __float2bfloat16(a0.y));
            *(__nv_bfloat162*)&u0.y = __nv_bfloat162(__float2bfloat16(a0.z), __float2bfloat16(a0.w));
            *(__nv_bfloat162*)&u0.z = __nv_bfloat162(__float2bfloat16(b0.x), __float2bfloat16(b0.y));
            *(__nv_bfloat162*)&u0.w = __nv_bfloat162(__float2bfloat16(b0.z), __float2bfloat16(b0.w));
            *(__nv_bfloat162*)&u1.x = __nv_bfloat162(__float2bfloat16(a1.x), __float2bfloat16(a1.y));
            *(__nv_bfloat162*)&u1.y = __nv_bfloat162(__float2bfloat16(a1.z), __float2bfloat16(a1.w));
            *(__nv_bfloat162*)&u1.z = __nv_bfloat162(__float2bfloat16(b1.x), __float2bfloat16(b1.y));
            *(__nv_bfloat162*)&u1.w = __nv_bfloat162(__float2bfloat16(b1.z), __float2bfloat16(b1.w));
#pragma unroll
            for (int e = 0; e < 2; e++) {
                size_t o = o0 + e;
                size_t v = o >> 8;
                int c8 = (int)(o & 255);
                size_t dst = (c8 < 128) ? v * 128 + c8 : CTXOFF4 + v * 128 + (c8 - 128);
                __stcs((uint4*)g_wbf + dst, e ? u1 : u0);
            }
        }
    }
    gsync(tgt);

    const size_t CTXOFF8 = (size_t)VDIM * 256;   // uint64-index of ctx-half region

    // ---------- decode loop ----------
    int word = 1;  // SOS
    for (int t = 0; t < NBOUND; t++) {
        const int par = t & 1;
        const int pold = par, pnew = par ^ 1;

        // ---- GRU: 16 warps = 4 rows/block x 4 k-slices ----
        {
            int g = w >> 2, sub = w & 3;
            int j = blk * 4 + g;
            if (j < 1024) {
                int k4 = sub * 64;
                const float4* xv = (const float4*)(emb_table + (size_t)word * 1024) + k4;
                const float4* hv = (const float4*)g_h[pold] + k4;
                const float4* m0 = (const float4*)(W_ih + (size_t)j * 1024) + k4;
                const float4* m1 = (const float4*)(W_ih + (size_t)(1024 + j) * 1024) + k4;
                const float4* m2 = (const float4*)(W_ih + (size_t)(2048 + j) * 1024) + k4;
                const float4* m3 = (const float4*)(W_hh + (size_t)j * 1024) + k4;
                const float4* m4p = (const float4*)(W_hh + (size_t)(1024 + j) * 1024) + k4;
                const float4* m5 = (const float4*)(W_hh + (size_t)(2048 + j) * 1024) + k4;
                float a0 = 0, a1 = 0, a2 = 0, a3 = 0, a4 = 0, a5 = 0;
#pragma unroll
                for (int i = 0; i < 2; i++) {
                    int k = lane + 32 * i;
                    float4 x = __ldg(xv + k);
                    float4 h = __ldcg(hv + k);
                    float4 m;
                    m = __ldg(m0 + k); a0 = fmaf(m.x, x.x, a0); a0 = fmaf(m.y, x.y, a0); a0 = fmaf(m.z, x.z, a0); a0 = fmaf(m.w, x.w, a0);
                    m = __ldg(m1 + k); a1 = fmaf(m.x, x.x, a1); a1 = fmaf(m.y, x.y, a1); a1 = fmaf(m.z, x.z, a1); a1 = fmaf(m.w, x.w, a1);
                    m = __ldg(m2 + k); a2 = fmaf(m.x, x.x, a2); a2 = fmaf(m.y, x.y, a2); a2 = fmaf(m.z, x.z, a2); a2 = fmaf(m.w, x.w, a2);
                    m = __ldg(m3 + k); a3 = fmaf(m.x, h.x, a3); a3 = fmaf(m.y, h.y, a3); a3 = fmaf(m.z, h.z, a3); a3 = fmaf(m.w, h.w, a3);
                    m = __ldg(m4p + k); a4 = fmaf(m.x, h.x, a4); a4 = fmaf(m.y, h.y, a4); a4 = fmaf(m.z, h.z, a4); a4 = fmaf(m.w, h.w, a4);
                    m = __ldg(m5 + k); a5 = fmaf(m.x, h.x, a5); a5 = fmaf(m.y, h.y, a5); a5 = fmaf(m.z, h.z, a5); a5 = fmaf(m.w, h.w, a5);
                }
                a0 = warp_sum(a0); a1 = warp_sum(a1); a2 = warp_sum(a2);
                a3 = warp_sum(a3); a4 = warp_sum(a4); a5 = warp_sum(a5);
                if (lane == 0) {
                    s_gru[g][sub][0] = a0; s_gru[g][sub][1] = a1; s_gru[g][sub][2] = a2;
                    s_gru[g][sub][3] = a3; s_gru[g][sub][4] = a4; s_gru[g][sub][5] = a5;
                }
            }
            __syncthreads();
            if (tid < 4) {
                int jo = blk * 4 + tid;
                if (jo < 1024) {
                    float D[6];
#pragma unroll
                    for (int d = 0; d < 6; d++)
                        D[d] = s_gru[tid][0][d] + s_gru[tid][1][d] + s_gru[tid][2][d] + s_gru[tid][3][d];
                    float gr = D[0] + __ldg(&b_ih[jo]);
                    float gz = D[1] + __ldg(&b_ih[1024 + jo]);
                    float gn = D[2] + __ldg(&b_ih[2048 + jo]);
                    float hr = D[3] + __ldg(&b_hh[jo]);
                    float hz = D[4] + __ldg(&b_hh[1024 + jo]);
                    float hn = D[5] + __ldg(&b_hh[2048 + jo]);
                    float r = sigmoid_fast(gr + hr);
                    float z = sigmoid_fast(gz + hz);
                    float n = tanh_fast(gn + r * hn);
                    float hold = __ldcg(&g_h[pold][jo]);
                    __stcg(&g_h[pnew][jo], (1.f - z) * n + z * hold);
                }
            }
        }
        gsync(tgt);
        if (blk == 0 && tid == 0) {
            atomicExch(&g_M[par ^ 1], 0u);
            atomicExch(&g_best[par ^ 1], 0ull);
        }

        // ---- phase 1: vocab h-half (blocks < NVB) || attention chain (blocks >= NVB) ----
        if (blk < NVB) {
            float* ms = s_As;
            for (int i = tid; i < 1024; i += NTHR) ms[i] = __ldcg(&g_h[pnew][i]);
            __syncthreads();
            const float4* m4 = (const float4*)ms;
            int gw1 = blk * 16 + w;
            for (int v = gw1; v < VDIM; v += NW1) {
                const unsigned long long* r8 = (const unsigned long long*)g_wbf + (size_t)v * 256;
                float acc = 0.f, ab = 0.f;
#pragma unroll
                for (int i = 0; i < 8; i++) {
                    int j = lane + 32 * i;
                    unsigned long long u = __ldcs(r8 + j);
                    float4 mm = m4[j];
                    unsigned lo = (unsigned)u, hi = (unsigned)(u >> 32);
                    float2 f0 = __bfloat1622float2(*(__nv_bfloat162*)&lo);
                    float2 f1 = __bfloat1622float2(*(__nv_bfloat162*)&hi);
                    acc = fmaf(f0.x, mm.x, acc); ab = fmaf(fabsf(f0.x), fabsf(mm.x), ab);
                    acc = fmaf(f0.y, mm.y, acc); ab = fmaf(fabsf(f0.y), fabsf(mm.y), ab);
                    acc = fmaf(f1.x, mm.z, acc); ab = fmaf(fabsf(f1.x), fabsf(mm.z), ab);
                    acc = fmaf(f1.y, mm.w, acc); ab = fmaf(fabsf(f1.y), fabsf(mm.w), ab);
                }
                acc = warp_sum(acc);
                ab = warp_sum(ab);
                if (lane == 0) { __stcg(&g_partA[v], acc); __stcg(&g_partB[v], ab); }
            }
        } else {
            const int cb = blk - NVB;   // 0..31
            // q: 512 chain warps, 2 rows each
            {
                int base = cb * 16 + w;
#pragma unroll
                for (int r = 0; r < 2; r++) {
                    int a = base + 512 * r;
                    const float4* mq = (const float4*)(Wq + (size_t)a * 1024);
                    const float4* hv = (const float4*)g_h[pnew];
                    float acc = 0.f;
#pragma unroll
                    for (int i = 0; i < 8; i++) {
                        int k = lane + 32 * i;
                        float4 m = __ldg(mq + k);
                        float4 h = __ldcg(hv + k);
                        acc = fmaf(m.x, h.x, acc); acc = fmaf(m.y, h.y, acc);
                        acc = fmaf(m.z, h.z, acc); acc = fmaf(m.w, h.w, acc);
                    }
                    acc = warp_sum(acc);
                    if (lane == 0) __stcg(&g_q[a], acc);
                }
            }
            subsync(stgt);
            // s: 4 rows per warp
            {
                int base = cb * 16 + w;
#pragma unroll
                for (int r = 0; r < 4; r++) {
                    int j = base + 512 * r;
                    const float4* ep = (const float4*)(g_eproj + (size_t)j * 1024);
                    const float4* qv = (const float4*)g_q;
                    const float4* vv = (const float4*)va;
                    float acc = 0.f;
#pragma unroll 4
                    for (int i = 0; i < 8; i++) {
                        int k = lane + 32 * i;
                        float4 e4 = __ldg(ep + k);
                        float4 q4 = __ldcg(qv + k);
                        float4 v4 = __ldg(vv + k);
                        acc = fmaf(tanh_fast(e4.x + q4.x), v4.x, acc);
                        acc = fmaf(tanh_fast(e4.y + q4.y), v4.y, acc);
                        acc = fmaf(tanh_fast(e4.z + q4.z), v4.z, acc);
                        acc = fmaf(tanh_fast(e4.w + q4.w), v4.w, acc);
                    }
                    acc = warp_sum(acc);
                    if (lane == 0) __stcg(&g_s[j], acc);
                }
            }
            subsync(stgt);
            // softmax stats (redundant per block) + weights out + ctx partial
            {
                float v4[4];
                float lm = -3.4e38f;
#pragma unroll
                for (int r = 0; r < 4; r++) {
                    v4[r] = __ldcg(&g_s[tid + 512 * r]);
                    lm = fmaxf(lm, v4[r]);
                }
#pragma unroll
                for (int o = 16; o; o >>= 1) lm = fmaxf(lm, __shfl_xor_sync(0xffffffffu, lm, o));
                if (lane == 0) s_red[w] = lm;
                __syncthreads();
                float m = s_red[0];
#pragma unroll
                for (int k = 1; k < 16; k++) m = fmaxf(m, s_red[k]);
                __syncthreads();
                float ls = 0.f;
#pragma unroll
                for (int r = 0; r < 4; r++) ls += expf(v4[r] - m);
                ls = warp_sum(ls);
                if (lane == 0) s_red[w] = ls;
                __syncthreads();
                float tot = s_red[0];
#pragma unroll
                for (int k = 1; k < 16; k++) tot += s_red[k];
                float inv = 1.f / tot;

                if (cb == 0) {
                    size_t base = (size_t)NBOUND + (size_t)t * SDIM;
#pragma unroll
                    for (int r = 0; r < 4; r++)
                        out[base + tid + 512 * r] = expf(v4[r] - m) * inv;
                }

                // ctx partial: sc = cb>>2 (s-chunk of 256), aq = cb&3 (a-chunk of 256)
                int sc = cb >> 2, aq = cb & 3;
                int a0 = aq * 256;
                float* sw = s_Bs;   // stage 256 weights + 512 partials
                if (tid < 256) {
                    int s = sc * 256 + tid;
                    sw[tid] = expf(__ldcg(&g_s[s]) - m) * inv;
                }
                __syncthreads();
                int al = tid & 255, sg = tid >> 8;   // sg in {0,1}
                float acc = 0.f;
                int sbase = sc * 256 + sg * 128;
#pragma unroll 4
                for (int ss = 0; ss < 128; ss++) {
                    acc = fmaf(sw[sg * 128 + ss],
                               __ldg(&emb[(size_t)(sbase + ss) * 1024 + a0 + al]), acc);
                }
                sw[256 + sg * 256 + al] = acc;
                __syncthreads();
                if (tid < 256)
                    __stcg(&g_ctx_part[sc][a0 + tid], sw[256 + tid] + sw[512 + tid]);
            }
        }
        gsync(tgt);   // join

        // ---- phase 2: all blocks: merge + ctx-half GEMV + bound ----
        float* ms = s_As;
        for (int i = tid; i < 1024; i += NTHR) ms[i] = __ldcg(&g_h[pnew][i]);
        for (int i = tid; i < 1024; i += NTHR) {
            float c = 0.f;
#pragma unroll
            for (int p = 0; p < 8; p++) c += __ldcg(&g_ctx_part[p][i]);
            ms[1024 + i] = c;
        }
        __syncthreads();
        const float4* m4 = (const float4*)ms;
        float wmax = -3.4e38f;
        {
            int gw2 = blk * 16 + w;
            for (int v = gw2; v < VDIM; v += NWTOT) {
                const unsigned long long* r8 =
                    (const unsigned long long*)g_wbf + CTXOFF8 + (size_t)v * 256;
                float acc = 0.f, ab = 0.f;
#pragma unroll
                for (int i = 0; i < 8; i++) {
                    int j = lane + 32 * i;
                    unsigned long long u = __ldcs(r8 + j);
                    float4 mm = m4[256 + j];
                    unsigned lo = (unsigned)u, hi = (unsigned)(u >> 32);
                    float2 f0 = __bfloat1622float2(*(__nv_bfloat162*)&lo);
                    float2 f1 = __bfloat1622float2(*(__nv_bfloat162*)&hi);
                    acc = fmaf(f0.x, mm.x, acc); ab = fmaf(fabsf(f0.x), fabsf(mm.x), ab);
                    acc = fmaf(f0.y, mm.y, acc); ab = fmaf(fabsf(f0.y), fabsf(mm.y), ab);
                    acc = fmaf(f1.x, mm.z, acc); ab = fmaf(fabsf(f1.x), fabsf(mm.z), ab);
                    acc = fmaf(f1.y, mm.w, acc); ab = fmaf(fabsf(f1.y), fabsf(mm.w), ab);
                }
                acc = warp_sum(acc);
                ab = warp_sum(ab);
                if (lane == 0) {
                    float A = acc + __ldcg(&g_partA[v]) + __ldg(&bout[v]);
                    float abt = ab + __ldcg(&g_partB[v]);
                    float B = fmaf(abt, 0.00390625f, 1e-4f);
                    __stcg(&g_ub[v], A + B);
                    wmax = fmaxf(wmax, A - B);
                }
            }
        }
#pragma unroll
        for (int o = 16; o; o >>= 1) wmax = fmaxf(wmax, __shfl_xor_sync(0xffffffffu, wmax, o));
        if (lane == 0) s_red[w] = wmax;
        __syncthreads();
        if (tid == 0) {
            float bm = s_red[0];
#pragma unroll
            for (int k = 1; k < 16; k++) bm = fmaxf(bm, s_red[k]);
            atomicMax(&g_M[par], enc_f(bm));
        }
        gsync(tgt);

        // ---- scan + exact fp32 rescore ----
        if (tid == 0) s_cnt = 0;
        __syncthreads();
        {
            float thr = dec_f(__ldcg(&g_M[par]));
            int i = blk * NTHR + tid;
            if (i < VDIM && __ldcg(&g_ub[i]) >= thr) {
                int p = atomicAdd(&s_cnt, 1);
                if (p < 32) s_cand[p] = i;
            }
        }
        __syncthreads();
        int nc = min(s_cnt, 32);
        for (int c = 0; c < nc; c++) {
            int v = s_cand[c];
            float4 rr = __ldg((const float4*)(Wout + (size_t)v * MERGED) + tid);
            float4 mm = m4[tid];
            float a = fmaf(rr.x, mm.x, fmaf(rr.y, mm.y, fmaf(rr.z, mm.z, rr.w * mm.w)));
            a = warp_sum(a);
            if (lane == 0) s_red[w] = a;
            __syncthreads();
            if (tid == 0) {
                float L = 0.f;
#pragma unroll
                for (int k = 0; k < 16; k++) L += s_red[k];
                L += __ldg(&bout[v]);
                unsigned long long pk =
                    ((unsigned long long)enc_f(L) << 32) |
                    (unsigned long long)(0xFFFFFFFFu - (unsigned)v);
                atomicMax(&g_best[par], pk);
            }
            __syncthreads();
        }
        gsync(tgt);

        if (tid == 0) {
            unsigned long long pk = __ldcg(&g_best[par]);
            int wd = (int)(0xFFFFFFFFu - (unsigned)(pk & 0xFFFFFFFFull));
            s_word = wd;
            if (blk == 0) out[t] = (float)wd;
        }
        __syncthreads();
        word = s_word;
    }
}

// ---------------- launch ----------------
extern "C" void kernel_launch(void* const* d_in, const int* in_sizes, int n_in,
                              void* d_out, int out_size) {
    const float* hidden     = (const float*)d_in[0];
    const float* embeddings = (const float*)d_in[1];
    const float* emb_table  = (const float*)d_in[2];
    const float* W_ih       = (const float*)d_in[3];
    const float* W_hh       = (const float*)d_in[4];
    const float* b_ih       = (const float*)d_in[5];
    const float* b_hh       = (const float*)d_in[6];
    const float* W_e        = (const float*)d_in[7];
    const float* W_q        = (const float*)d_in[8];
    const float* b_a        = (const float*)d_in[9];
    const float* v_a        = (const float*)d_in[10];
    const float* W_out      = (const float*)d_in[11];
    const float* b_out      = (const float*)d_in[12];
    float* out = (float*)d_out;

    k_mega<<<NBLK, NTHR>>>(hidden, embeddings, emb_table, W_ih, W_hh, b_ih, b_hh,
                           W_e, W_q, b_a, v_a, W_out, b_out, out);
}

// round 8
// speedup vs baseline: 1.0974x; 1.0974x over previous
#include <cuda_runtime.h>
#include <cuda_bf16.h>
#include <cstdint>

#define HDIM 1024
#define SDIM 2048
#define VDIM 50257
#define NBOUND 25
#define MERGED 2048
#define NBLK 296           // 148 SMs x 2 co-resident blocks
#define NTHR 512
#define NWTOT (NBLK * 16)  // 4736 warps

// ---------------- device scratch ----------------
__device__ __align__(16) float g_h[2][HDIM];
__device__ __align__(16) float g_q[HDIM];
__device__ __align__(16) float g_s[SDIM];
__device__ __align__(16) float g_ctx_part[8][HDIM];
__device__ __align__(16) float g_eproj[(size_t)SDIM * HDIM];          // 8 MB
__device__ __align__(16) __nv_bfloat16 g_wbf[(size_t)VDIM * MERGED];  // 206 MB
__device__ unsigned g_M[2];
__device__ unsigned long long g_best[2];
__device__ unsigned g_bar_count, g_bar_phase;

// ---------------- helpers ----------------
__device__ __forceinline__ float warp_sum(float v) {
#pragma unroll
    for (int o = 16; o; o >>= 1) v += __shfl_xor_sync(0xffffffffu, v, o);
    return v;
}
__device__ __forceinline__ unsigned enc_f(float f) {
    unsigned b = __float_as_uint(f);
    return (b & 0x80000000u) ? ~b : (b | 0x80000000u);
}
__device__ __forceinline__ float dec_f(unsigned u) {
    unsigned b = (u & 0x80000000u) ? (u ^ 0x80000000u) : ~u;
    return __uint_as_float(b);
}
__device__ __forceinline__ float exp2_fast(float y) {
    y = fminf(fmaxf(y, -60.f), 60.f);
    float n = rintf(y);
    float f = y - n;
    float p = 1.5403530e-4f;
    p = fmaf(p, f, 1.3333558e-3f);
    p = fmaf(p, f, 9.6181291e-3f);
    p = fmaf(p, f, 5.5504109e-2f);
    p = fmaf(p, f, 2.4022651e-1f);
    p = fmaf(p, f, 6.9314718e-1f);
    p = fmaf(p, f, 1.0f);
    return __int_as_float(((int)n + 127) << 23) * p;
}
__device__ __forceinline__ float tanh_fast(float x) {
    float e = exp2_fast(x * 2.885390081777927f);
    return 1.f - 2.f / (e + 1.f);
}
__device__ __forceinline__ float sigmoid_fast(float x) {
    float e = exp2_fast(-1.4426950408889634f * x);
    return 1.f / (1.f + e);
}

// grid-wide barrier
__device__ __forceinline__ void gsync(unsigned& tgt) {
    __syncthreads();
    if (threadIdx.x == 0) {
        __threadfence();
        unsigned v = atomicAdd(&g_bar_count, 1u);
        if (v == NBLK - 1) {
            g_bar_count = 0;
            asm volatile("st.release.gpu.u32 [%0], %1;" :: "l"(&g_bar_phase), "r"(tgt) : "memory");
        } else {
            unsigned p;
            do {
                asm volatile("ld.acquire.gpu.u32 %0, [%1];" : "=r"(p) : "l"(&g_bar_phase) : "memory");
            } while ((int)(p - tgt) < 0);
        }
    }
    __syncthreads();
    tgt++;
}

// ---------------- the persistent mega-kernel ----------------
__global__ __launch_bounds__(NTHR, 2) void k_mega(
    const float* __restrict__ hidden, const float* __restrict__ emb,
    const float* __restrict__ emb_table,
    const float* __restrict__ W_ih, const float* __restrict__ W_hh,
    const float* __restrict__ b_ih, const float* __restrict__ b_hh,
    const float* __restrict__ We, const float* __restrict__ Wq,
    const float* __restrict__ ba, const float* __restrict__ va,
    const float* __restrict__ Wout, const float* __restrict__ bout,
    float* __restrict__ out)
{
    __shared__ __align__(16) float s_As[128 * 36];   // eproj A tile; reused as merge vec
    __shared__ __align__(16) float s_Bs[64 * 33];    // eproj B tile
    __shared__ float s_gru[4][4][6];
    __shared__ float s_red[16];
    __shared__ float s_ub[16][11];                   // per-warp row upper bounds
    __shared__ int s_cand[32];
    __shared__ int s_cnt;
    __shared__ int s_word;

    const int tid = threadIdx.x;
    const int blk = blockIdx.x;
    const int w = tid >> 5, lane = tid & 31;
    const int gw = blk * 16 + w;

    unsigned tgt = *((volatile unsigned*)&g_bar_phase) + 1;

    // ---------- phase 0: init + (eproj || quant), SM-paired split ----------
    if (blk == 0 && tid < 2) { g_M[tid] = 0u; g_best[tid] = 0ull; }
    if (blk == 1) {
        for (int i = tid; i < HDIM; i += NTHR) g_h[0][i] = hidden[i];
    }

    if (blk < 148) {
        // eproj: blocks 0..147 (one per SM); tiles blk and blk+148
        for (int tile = blk; tile < 256; tile += 148) {
            const int ts0 = (tile >> 4) * 128;
            const int ta0 = (tile & 15) * 64;
            const int ts = tid >> 4;
            const int ta = tid & 15;
            float acc[4][4];
#pragma unroll
            for (int i = 0; i < 4; i++)
#pragma unroll
                for (int j = 0; j < 4; j++) acc[i][j] = 0.f;
            for (int kt = 0; kt < 1024; kt += 32) {
#pragma unroll
                for (int r = 0; r < 8; r++) {
                    int e0 = tid + NTHR * r;
                    int si = e0 >> 5, kk = e0 & 31;
                    s_As[si * 36 + kk] = emb[(size_t)(ts0 + si) * 1024 + kt + kk];
                }
#pragma unroll
                for (int r = 0; r < 4; r++) {
                    int e0 = tid + NTHR * r;
                    int ai = e0 >> 5, kk = e0 & 31;
                    s_Bs[ai * 33 + kk] = We[(size_t)(ta0 + ai) * 1024 + kt + kk];
                }
                __syncthreads();
#pragma unroll
                for (int k = 0; k < 32; k++) {
                    float a0 = s_As[ts * 36 + k];
                    float a1 = s_As[(ts + 32) * 36 + k];
                    float a2 = s_As[(ts + 64) * 36 + k];
                    float a3 = s_As[(ts + 96) * 36 + k];
                    float b0 = s_Bs[(ta * 4 + 0) * 33 + k];
                    float b1 = s_Bs[(ta * 4 + 1) * 33 + k];
                    float b2 = s_Bs[(ta * 4 + 2) * 33 + k];
                    float b3 = s_Bs[(ta * 4 + 3) * 33 + k];
                    acc[0][0] = fmaf(a0, b0, acc[0][0]); acc[0][1] = fmaf(a0, b1, acc[0][1]);
                    acc[0][2] = fmaf(a0, b2, acc[0][2]); acc[0][3] = fmaf(a0, b3, acc[0][3]);
                    acc[1][0] = fmaf(a1, b0, acc[1][0]); acc[1][1] = fmaf(a1, b1, acc[1][1]);
                    acc[1][2] = fmaf(a1, b2, acc[1][2]); acc[1][3] = fmaf(a1, b3, acc[1][3]);
                    acc[2][0] = fmaf(a2, b0, acc[2][0]); acc[2][1] = fmaf(a2, b1, acc[2][1]);
                    acc[2][2] = fmaf(a2, b2, acc[2][2]); acc[2][3] = fmaf(a2, b3, acc[2][3]);
                    acc[3][0] = fmaf(a3, b0, acc[3][0]); acc[3][1] = fmaf(a3, b1, acc[3][1]);
                    acc[3][2] = fmaf(a3, b2, acc[3][2]); acc[3][3] = fmaf(a3, b3, acc[3][3]);
                }
                __syncthreads();
            }
            float4 bb = __ldg((const float4*)(ba + ta0) + ta);
#pragma unroll
            for (int i = 0; i < 4; i++) {
                float4 o = make_float4(acc[i][0] + bb.x, acc[i][1] + bb.y,
                                       acc[i][2] + bb.z, acc[i][3] + bb.w);
                *(float4*)&g_eproj[(size_t)(ts0 + ts + 32 * i) * 1024 + ta0 + ta * 4] = o;
            }
            __syncthreads();
        }
    } else {
        // quant: blocks 148..295, 2 uint4 outputs per iteration (deep MLP)
        const size_t np = (size_t)VDIM * MERGED / 16;
        for (size_t ip = (size_t)(blk - 148) * NTHR + tid; ip < np;
             ip += (size_t)148 * NTHR) {
            const float4* p = (const float4*)Wout + ip * 4;
            float4 a0 = __ldcs(p), b0 = __ldcs(p + 1);
            float4 a1 = __ldcs(p + 2), b1 = __ldcs(p + 3);
            uint4 u0, u1;
            *(__nv_bfloat162*)&u0.x = __nv_bfloat162(__float2bfloat16(a0.x), __float2bfloat16(a0.y));
            *(__nv_bfloat162*)&u0.y = __nv_bfloat162(__float2bfloat16(a0.z), __float2bfloat16(a0.w));
            *(__nv_bfloat162*)&u0.z = __nv_bfloat162(__float2bfloat16(b0.x), __float2bfloat16(b0.y));
            *(__nv_bfloat162*)&u0.w = __nv_bfloat162(__float2bfloat16(b0.z), __float2bfloat16(b0.w));
            *(__nv_bfloat162*)&u1.x = __nv_bfloat162(__float2bfloat16(a1.x), __float2bfloat16(a1.y));
            *(__nv_bfloat162*)&u1.y = __nv_bfloat162(__float2bfloat16(a1.z), __float2bfloat16(a1.w));
            *(__nv_bfloat162*)&u1.z = __nv_bfloat162(__float2bfloat16(b1.x), __float2bfloat16(b1.y));
            *(__nv_bfloat162*)&u1.w = __nv_bfloat162(__float2bfloat16(b1.z), __float2bfloat16(b1.w));
            __stcs((uint4*)g_wbf + ip * 2, u0);
            __stcs((uint4*)g_wbf + ip * 2 + 1, u1);
        }
    }
    gsync(tgt);

    // ---------- decode loop ----------
    int word = 1;  // SOS
    for (int t = 0; t < NBOUND; t++) {
        const int par = t & 1;
        const int pold = par, pnew = par ^ 1;

        // ---- GRU: 16 warps = 4 rows/block x 4 k-slices ----
        {
            int g = w >> 2, sub = w & 3;
            int j = blk * 4 + g;
            if (j < 1024) {
                int k4 = sub * 64;
                const float4* xv = (const float4*)(emb_table + (size_t)word * 1024) + k4;
                const float4* hv = (const float4*)g_h[pold] + k4;
                const float4* m0 = (const float4*)(W_ih + (size_t)j * 1024) + k4;
                const float4* m1 = (const float4*)(W_ih + (size_t)(1024 + j) * 1024) + k4;
                const float4* m2 = (const float4*)(W_ih + (size_t)(2048 + j) * 1024) + k4;
                const float4* m3 = (const float4*)(W_hh + (size_t)j * 1024) + k4;
                const float4* m4p = (const float4*)(W_hh + (size_t)(1024 + j) * 1024) + k4;
                const float4* m5 = (const float4*)(W_hh + (size_t)(2048 + j) * 1024) + k4;
                float a0 = 0, a1 = 0, a2 = 0, a3 = 0, a4 = 0, a5 = 0;
#pragma unroll
                for (int i = 0; i < 2; i++) {
                    int k = lane + 32 * i;
                    float4 x = __ldg(xv + k);
                    float4 h = __ldcg(hv + k);
                    float4 m;
                    m = __ldg(m0 + k); a0 = fmaf(m.x, x.x, a0); a0 = fmaf(m.y, x.y, a0); a0 = fmaf(m.z, x.z, a0); a0 = fmaf(m.w, x.w, a0);
                    m = __ldg(m1 + k); a1 = fmaf(m.x, x.x, a1); a1 = fmaf(m.y, x.y, a1); a1 = fmaf(m.z, x.z, a1); a1 = fmaf(m.w, x.w, a1);
                    m = __ldg(m2 + k); a2 = fmaf(m.x, x.x, a2); a2 = fmaf(m.y, x.y, a2); a2 = fmaf(m.z, x.z, a2); a2 = fmaf(m.w, x.w, a2);
                    m = __ldg(m3 + k); a3 = fmaf(m.x, h.x, a3); a3 = fmaf(m.y, h.y, a3); a3 = fmaf(m.z, h.z, a3); a3 = fmaf(m.w, h.w, a3);
                    m = __ldg(m4p + k); a4 = fmaf(m.x, h.x, a4); a4 = fmaf(m.y, h.y, a4); a4 = fmaf(m.z, h.z, a4); a4 = fmaf(m.w, h.w, a4);
                    m = __ldg(m5 + k); a5 = fmaf(m.x, h.x, a5); a5 = fmaf(m.y, h.y, a5); a5 = fmaf(m.z, h.z, a5); a5 = fmaf(m.w, h.w, a5);
                }
                a0 = warp_sum(a0); a1 = warp_sum(a1); a2 = warp_sum(a2);
                a3 = warp_sum(a3); a4 = warp_sum(a4); a5 = warp_sum(a5);
                if (lane == 0) {
                    s_gru[g][sub][0] = a0; s_gru[g][sub][1] = a1; s_gru[g][sub][2] = a2;
                    s_gru[g][sub][3] = a3; s_gru[g][sub][4] = a4; s_gru[g][sub][5] = a5;
                }
            }
            __syncthreads();
            if (tid < 4) {
                int jo = blk * 4 + tid;
                if (jo < 1024) {
                    float D[6];
#pragma unroll
                    for (int d = 0; d < 6; d++)
                        D[d] = s_gru[tid][0][d] + s_gru[tid][1][d] + s_gru[tid][2][d] + s_gru[tid][3][d];
                    float gr = D[0] + __ldg(&b_ih[jo]);
                    float gz = D[1] + __ldg(&b_ih[1024 + jo]);
                    float gn = D[2] + __ldg(&b_ih[2048 + jo]);
                    float hr = D[3] + __ldg(&b_hh[jo]);
                    float hz = D[4] + __ldg(&b_hh[1024 + jo]);
                    float hn = D[5] + __ldg(&b_hh[2048 + jo]);
                    float r = sigmoid_fast(gr + hr);
                    float z = sigmoid_fast(gz + hz);
                    float n = tanh_fast(gn + r * hn);
                    float hold = __ldcg(&g_h[pold][jo]);
                    __stcg(&g_h[pnew][jo], (1.f - z) * n + z * hold);
                }
            }
        }
        gsync(tgt);
        if (blk == 0 && tid == 0) {
            atomicExch(&g_M[par ^ 1], 0u);
            atomicExch(&g_best[par ^ 1], 0ull);
        }

        // ---- q[a] = h_new . Wq[a,:] ----
        {
            int a = w * NBLK + blk;
            if (w < 4 && a < 1024) {
                const float4* mq = (const float4*)(Wq + (size_t)a * 1024);
                const float4* hv = (const float4*)g_h[pnew];
                float acc = 0.f;
#pragma unroll
                for (int i = 0; i < 8; i++) {
                    int k = lane + 32 * i;
                    float4 m = __ldg(mq + k);
                    float4 h = __ldcg(hv + k);
                    acc = fmaf(m.x, h.x, acc); acc = fmaf(m.y, h.y, acc);
                    acc = fmaf(m.z, h.z, acc); acc = fmaf(m.w, h.w, acc);
                }
                acc = warp_sum(acc);
                if (lane == 0) __stcg(&g_q[a], acc);
            }
        }
        gsync(tgt);

        // ---- s[j] = sum_a tanh(eproj[j,a] + q[a]) * v_a[a] ----
        {
            int j = w * NBLK + blk;
            if (w < 7 && j < 2048) {
                const float4* ep = (const float4*)(g_eproj + (size_t)j * 1024);
                const float4* qv = (const float4*)g_q;
                const float4* vv = (const float4*)va;
                float acc = 0.f;
#pragma unroll 4
                for (int i = 0; i < 8; i++) {
                    int k = lane + 32 * i;
                    float4 e4 = __ldg(ep + k);
                    float4 q4 = __ldcg(qv + k);
                    float4 v4 = __ldg(vv + k);
                    acc = fmaf(tanh_fast(e4.x + q4.x), v4.x, acc);
                    acc = fmaf(tanh_fast(e4.y + q4.y), v4.y, acc);
                    acc = fmaf(tanh_fast(e4.z + q4.z), v4.z, acc);
                    acc = fmaf(tanh_fast(e4.w + q4.w), v4.w, acc);
                }
                acc = warp_sum(acc);
                if (lane == 0) __stcg(&g_s[j], acc);
            }
        }
        gsync(tgt);

        // ---- softmax (redundant stats) + ctx partials + weights output ----
        if (blk < 128) {
            float v4[4];
            float lm = -3.4e38f;
#pragma unroll
            for (int r = 0; r < 4; r++) {
                v4[r] = __ldcg(&g_s[tid + 512 * r]);
                lm = fmaxf(lm, v4[r]);
            }
#pragma unroll
            for (int o = 16; o; o >>= 1) lm = fmaxf(lm, __shfl_xor_sync(0xffffffffu, lm, o));
            if (lane == 0) s_red[w] = lm;
            __syncthreads();
            float m = s_red[0];
#pragma unroll
            for (int k = 1; k < 16; k++) m = fmaxf(m, s_red[k]);
            __syncthreads();
            float ls = 0.f;
#pragma unroll
            for (int r = 0; r < 4; r++) ls += expf(v4[r] - m);
            ls = warp_sum(ls);
            if (lane == 0) s_red[w] = ls;
            __syncthreads();
            float tot = s_red[0];
#pragma unroll
            for (int k = 1; k < 16; k++) tot += s_red[k];
            float inv = 1.f / tot;

            if (blk == 0) {
                size_t base = (size_t)NBOUND + (size_t)t * SDIM;
#pragma unroll
                for (int r = 0; r < 4; r++)
                    out[base + tid + 512 * r] = expf(v4[r] - m) * inv;
            }

            int sc = blk >> 4;
            int ac = blk & 15;
            int a0 = ac * 64;
            int g = tid >> 6, al = tid & 63;
            float acc = 0.f;
            int sb = sc * 256 + g * 32;
            for (int ss = 0; ss < 32; ss++) {
                int s = sb + ss;
                float wv = expf(__ldcg(&g_s[s]) - m) * inv;
                acc = fmaf(wv, __ldg(&emb[(size_t)s * 1024 + a0 + al]), acc);
            }
            float* sred = s_As;
            sred[g * 64 + al] = acc;
            __syncthreads();
            if (tid < 64) {
                float c = 0.f;
#pragma unroll
                for (int gg = 0; gg < 8; gg++) c += sred[gg * 64 + tid];
                __stcg(&g_ctx_part[sc][a0 + tid], c);
            }
        }
        gsync(tgt);

        // ---- vocab: bf16 GEMV + bounds (bounds kept in smem) ----
        float* ms = s_As;
        for (int i = tid; i < 1024; i += NTHR) ms[i] = __ldcg(&g_h[pnew][i]);
        for (int i = tid; i < 1024; i += NTHR) {
            float c = 0.f;
#pragma unroll
            for (int p = 0; p < 8; p++) c += __ldcg(&g_ctx_part[p][i]);
            ms[1024 + i] = c;
        }
        __syncthreads();
        const float4* m4 = (const float4*)ms;
        float wmax = -3.4e38f;
        {
            int r = 0;
            for (int v = gw; v < VDIM; v += NWTOT, r++) {
                const unsigned long long* r8 =
                    (const unsigned long long*)(g_wbf + (size_t)v * MERGED);
                float acc = 0.f, ab = 0.f;
#pragma unroll 8
                for (int i = 0; i < 16; i++) {
                    unsigned long long u = __ldcs(r8 + lane + 32 * i);
                    float4 mm = m4[lane + 32 * i];
                    unsigned lo = (unsigned)u, hi = (unsigned)(u >> 32);
                    float2 f0 = __bfloat1622float2(*(__nv_bfloat162*)&lo);
                    float2 f1 = __bfloat1622float2(*(__nv_bfloat162*)&hi);
                    acc = fmaf(f0.x, mm.x, acc); ab = fmaf(fabsf(f0.x), fabsf(mm.x), ab);
                    acc = fmaf(f0.y, mm.y, acc); ab = fmaf(fabsf(f0.y), fabsf(mm.y), ab);
                    acc = fmaf(f1.x, mm.z, acc); ab = fmaf(fabsf(f1.x), fabsf(mm.z), ab);
                    acc = fmaf(f1.y, mm.w, acc); ab = fmaf(fabsf(f1.y), fabsf(mm.w), ab);
                }
                acc = warp_sum(acc);
                ab = warp_sum(ab);
                if (lane == 0) {
                    float A = acc + __ldg(&bout[v]);
                    float B = fmaf(ab, 0.00390625f, 1e-4f);
                    s_ub[w][r] = A + B;
                    wmax = fmaxf(wmax, A - B);
                }
            }
            // pad remaining slots so scan can read unconditionally
            if (lane == 0) for (; r < 11; r++) s_ub[w][r] = -3.4e38f;
        }
#pragma unroll
        for (int o = 16; o; o >>= 1) wmax = fmaxf(wmax, __shfl_xor_sync(0xffffffffu, wmax, o));
        if (lane == 0) s_red[w] = wmax;
        __syncthreads();
        if (tid == 0) {
            float bm = s_red[0];
#pragma unroll
            for (int k = 1; k < 16; k++) bm = fmaxf(bm, s_red[k]);
            atomicMax(&g_M[par], enc_f(bm));
            s_cnt = 0;
        }
        gsync(tgt);

        // ---- scan own smem bounds + exact fp32 rescore ----
        {
            float thr = dec_f(__ldcg(&g_M[par]));
            if (lane == 0) {
#pragma unroll
                for (int r = 0; r < 11; r++) {
                    if (s_ub[w][r] >= thr) {
                        int p = atomicAdd(&s_cnt, 1);
                        if (p < 32) s_cand[p] = gw + r * NWTOT;
                    }
                }
            }
        }
        __syncthreads();
        int nc = min(s_cnt, 32);
        for (int c = 0; c < nc; c++) {
            int v = s_cand[c];
            float4 rr = __ldg((const float4*)(Wout + (size_t)v * MERGED) + tid);
            float4 mm = m4[tid];
            float a = fmaf(rr.x, mm.x, fmaf(rr.y, mm.y, fmaf(rr.z, mm.z, rr.w * mm.w)));
            a = warp_sum(a);
            if (lane == 0) s_red[w] = a;
            __syncthreads();
            if (tid == 0) {
                float L = 0.f;
#pragma unroll
                for (int k = 0; k < 16; k++) L += s_red[k];
                L += __ldg(&bout[v]);
                unsigned long long pk =
                    ((unsigned long long)enc_f(L) << 32) |
                    (unsigned long long)(0xFFFFFFFFu - (unsigned)v);
                atomicMax(&g_best[par], pk);
            }
            __syncthreads();
        }
        gsync(tgt);

        if (tid == 0) {
            unsigned long long pk = __ldcg(&g_best[par]);
            int wd = (int)(0xFFFFFFFFu - (unsigned)(pk & 0xFFFFFFFFull));
            s_word = wd;
            if (blk == 0) out[t] = (float)wd;
        }
        __syncthreads();
        word = s_word;
    }
}

// ---------------- launch ----------------
extern "C" void kernel_launch(void* const* d_in, const int* in_sizes, int n_in,
                              void* d_out, int out_size) {
    const float* hidden     = (const float*)d_in[0];
    const float* embeddings = (const float*)d_in[1];
    const float* emb_table  = (const float*)d_in[2];
    const float* W_ih       = (const float*)d_in[3];
    const float* W_hh       = (const float*)d_in[4];
    const float* b_ih       = (const float*)d_in[5];
    const float* b_hh       = (const float*)d_in[6];
    const float* W_e        = (const float*)d_in[7];
    const float* W_q        = (const float*)d_in[8];
    const float* b_a        = (const float*)d_in[9];
    const float* v_a        = (const float*)d_in[10];
    const float* W_out      = (const float*)d_in[11];
    const float* b_out      = (const float*)d_in[12];
    float* out = (float*)d_out;

    k_mega<<<NBLK, NTHR>>>(hidden, embeddings, emb_table, W_ih, W_hh, b_ih, b_hh,
                           W_e, W_q, b_a, v_a, W_out, b_out, out);
}

// round 9
// speedup vs baseline: 1.1335x; 1.0329x over previous
#include <cuda_runtime.h>
#include <cuda_bf16.h>
#include <cstdint>

#define HDIM 1024
#define SDIM 2048
#define VDIM 50257
#define NBOUND 25
#define MERGED 2048
#define NBLK 296           // 148 SMs x 2 co-resident blocks
#define NTHR 512
#define NWTOT (NBLK * 16)  // 4736 warps

// ---------------- device scratch ----------------
__device__ __align__(16) float g_h[2][HDIM];
__device__ __align__(16) float g_q[HDIM];
__device__ __align__(16) float g_s[SDIM];
__device__ __align__(16) float g_ctx_part[8][HDIM];
__device__ __align__(16) float g_eproj[(size_t)SDIM * HDIM];          // 8 MB
__device__ __align__(16) __nv_bfloat16 g_wbf[(size_t)VDIM * MERGED];  // 206 MB
__device__ unsigned g_M[2];
__device__ unsigned long long g_best[2];
__device__ unsigned g_bar_count, g_bar_phase;

// ---------------- helpers ----------------
__device__ __forceinline__ float warp_sum(float v) {
#pragma unroll
    for (int o = 16; o; o >>= 1) v += __shfl_xor_sync(0xffffffffu, v, o);
    return v;
}
__device__ __forceinline__ unsigned enc_f(float f) {
    unsigned b = __float_as_uint(f);
    return (b & 0x80000000u) ? ~b : (b | 0x80000000u);
}
__device__ __forceinline__ float dec_f(unsigned u) {
    unsigned b = (u & 0x80000000u) ? (u ^ 0x80000000u) : ~u;
    return __uint_as_float(b);
}
__device__ __forceinline__ float exp2_fast(float y) {
    y = fminf(fmaxf(y, -60.f), 60.f);
    float n = rintf(y);
    float f = y - n;
    float p = 1.5403530e-4f;
    p = fmaf(p, f, 1.3333558e-3f);
    p = fmaf(p, f, 9.6181291e-3f);
    p = fmaf(p, f, 5.5504109e-2f);
    p = fmaf(p, f, 2.4022651e-1f);
    p = fmaf(p, f, 6.9314718e-1f);
    p = fmaf(p, f, 1.0f);
    return __int_as_float(((int)n + 127) << 23) * p;
}
__device__ __forceinline__ float tanh_fast(float x) {
    float e = exp2_fast(x * 2.885390081777927f);
    return 1.f - 2.f / (e + 1.f);
}
__device__ __forceinline__ float sigmoid_fast(float x) {
    float e = exp2_fast(-1.4426950408889634f * x);
    return 1.f / (1.f + e);
}

// grid-wide barrier
__device__ __forceinline__ void gsync(unsigned& tgt) {
    __syncthreads();
    if (threadIdx.x == 0) {
        __threadfence();
        unsigned v = atomicAdd(&g_bar_count, 1u);
        if (v == NBLK - 1) {
            g_bar_count = 0;
            asm volatile("st.release.gpu.u32 [%0], %1;" :: "l"(&g_bar_phase), "r"(tgt) : "memory");
        } else {
            unsigned p;
            do {
                asm volatile("ld.acquire.gpu.u32 %0, [%1];" : "=r"(p) : "l"(&g_bar_phase) : "memory");
            } while ((int)(p - tgt) < 0);
        }
    }
    __syncthreads();
    tgt++;
}

__device__ __forceinline__ void quant_one(const float* __restrict__ Wout, size_t idx) {
    const float4* p = (const float4*)Wout + idx * 2;
    float4 a = __ldcs(p);
    float4 b = __ldcs(p + 1);
    uint4 o;
    *(__nv_bfloat162*)&o.x = __nv_bfloat162(__float2bfloat16(a.x), __float2bfloat16(a.y));
    *(__nv_bfloat162*)&o.y = __nv_bfloat162(__float2bfloat16(a.z), __float2bfloat16(a.w));
    *(__nv_bfloat162*)&o.z = __nv_bfloat162(__float2bfloat16(b.x), __float2bfloat16(b.y));
    *(__nv_bfloat162*)&o.w = __nv_bfloat162(__float2bfloat16(b.z), __float2bfloat16(b.w));
    __stcs((uint4*)g_wbf + idx, o);
}

// ---------------- the persistent mega-kernel ----------------
__global__ __launch_bounds__(NTHR, 2) void k_mega(
    const float* __restrict__ hidden, const float* __restrict__ emb,
    const float* __restrict__ emb_table,
    const float* __restrict__ W_ih, const float* __restrict__ W_hh,
    const float* __restrict__ b_ih, const float* __restrict__ b_hh,
    const float* __restrict__ We, const float* __restrict__ Wq,
    const float* __restrict__ ba, const float* __restrict__ va,
    const float* __restrict__ Wout, const float* __restrict__ bout,
    float* __restrict__ out)
{
    __shared__ __align__(16) float s_As[128 * 36];   // eproj A tile; reused as merge vec
    __shared__ __align__(16) float s_Bs[64 * 33];    // eproj B tile
    __shared__ float s_gru[4][4][6];
    __shared__ float s_red[16];
    __shared__ float s_ub[16][11];                   // per-warp row upper bounds
    __shared__ int s_cand[32];
    __shared__ int s_cnt;
    __shared__ int s_word;

    const int tid = threadIdx.x;
    const int blk = blockIdx.x;
    const int w = tid >> 5, lane = tid & 31;
    const int gw = blk * 16 + w;

    unsigned tgt = *((volatile unsigned*)&g_bar_phase) + 1;

    // ---------- phase 0: init + FUSED (eproj FMA || quant DRAM) in every block ----------
    if (blk == 0 && tid < 2) { g_M[tid] = 0u; g_best[tid] = 0ull; }
    if (blk == 1) {
        for (int i = tid; i < HDIM; i += NTHR) g_h[0][i] = hidden[i];
    }

    const size_t n8 = (size_t)VDIM * MERGED / 8;     // 8-bf16 quant chunks
    const size_t QSTR = (size_t)NBLK * NTHR;
    size_t qidx = (size_t)blk * NTHR + tid;

    if (blk < 256) {
        // eproj: one 128x64 tile; 3 quant chunks per thread per k-iteration hide under FMA
        const int ts0 = (blk >> 4) * 128;
        const int ta0 = (blk & 15) * 64;
        const int ts = tid >> 4;
        const int ta = tid & 15;
        float acc[4][4];
#pragma unroll
        for (int i = 0; i < 4; i++)
#pragma unroll
            for (int j = 0; j < 4; j++) acc[i][j] = 0.f;
        for (int kt = 0; kt < 1024; kt += 32) {
#pragma unroll
            for (int r = 0; r < 8; r++) {
                int e0 = tid + NTHR * r;
                int si = e0 >> 5, kk = e0 & 31;
                s_As[si * 36 + kk] = emb[(size_t)(ts0 + si) * 1024 + kt + kk];
            }
#pragma unroll
            for (int r = 0; r < 4; r++) {
                int e0 = tid + NTHR * r;
                int ai = e0 >> 5, kk = e0 & 31;
                s_Bs[ai * 33 + kk] = We[(size_t)(ta0 + ai) * 1024 + kt + kk];
            }
            __syncthreads();
#pragma unroll
            for (int k = 0; k < 32; k++) {
                float a0 = s_As[ts * 36 + k];
                float a1 = s_As[(ts + 32) * 36 + k];
                float a2 = s_As[(ts + 64) * 36 + k];
                float a3 = s_As[(ts + 96) * 36 + k];
                float b0 = s_Bs[(ta * 4 + 0) * 33 + k];
                float b1 = s_Bs[(ta * 4 + 1) * 33 + k];
                float b2 = s_Bs[(ta * 4 + 2) * 33 + k];
                float b3 = s_Bs[(ta * 4 + 3) * 33 + k];
                acc[0][0] = fmaf(a0, b0, acc[0][0]); acc[0][1] = fmaf(a0, b1, acc[0][1]);
                acc[0][2] = fmaf(a0, b2, acc[0][2]); acc[0][3] = fmaf(a0, b3, acc[0][3]);
                acc[1][0] = fmaf(a1, b0, acc[1][0]); acc[1][1] = fmaf(a1, b1, acc[1][1]);
                acc[1][2] = fmaf(a1, b2, acc[1][2]); acc[1][3] = fmaf(a1, b3, acc[1][3]);
                acc[2][0] = fmaf(a2, b0, acc[2][0]); acc[2][1] = fmaf(a2, b1, acc[2][1]);
                acc[2][2] = fmaf(a2, b2, acc[2][2]); acc[2][3] = fmaf(a2, b3, acc[2][3]);
                acc[3][0] = fmaf(a3, b0, acc[3][0]); acc[3][1] = fmaf(a3, b1, acc[3][1]);
                acc[3][2] = fmaf(a3, b2, acc[3][2]); acc[3][3] = fmaf(a3, b3, acc[3][3]);
            }
            // interleaved quant: DRAM work hidden under the FMA above / next tile
#pragma unroll
            for (int e = 0; e < 3; e++) {
                if (qidx < n8) quant_one(Wout, qidx);
                qidx += QSTR;
            }
            __syncthreads();
        }
        float4 bb = __ldg((const float4*)(ba + ta0) + ta);
#pragma unroll
        for (int i = 0; i < 4; i++) {
            float4 o = make_float4(acc[i][0] + bb.x, acc[i][1] + bb.y,
                                   acc[i][2] + bb.z, acc[i][3] + bb.w);
            *(float4*)&g_eproj[(size_t)(ts0 + ts + 32 * i) * 1024 + ta0 + ta * 4] = o;
        }
    } else {
        while (qidx < n8) { quant_one(Wout, qidx); qidx += QSTR; }
    }
    gsync(tgt);

    // ---------- decode loop ----------
    int word = 1;  // SOS
    for (int t = 0; t < NBOUND; t++) {
        const int par = t & 1;
        const int pold = par, pnew = par ^ 1;

        // ---- GRU: 16 warps = 4 rows/block x 4 k-slices ----
        {
            int g = w >> 2, sub = w & 3;
            int j = blk * 4 + g;
            if (j < 1024) {
                int k4 = sub * 64;
                const float4* xv = (const float4*)(emb_table + (size_t)word * 1024) + k4;
                const float4* hv = (const float4*)g_h[pold] + k4;
                const float4* m0 = (const float4*)(W_ih + (size_t)j * 1024) + k4;
                const float4* m1 = (const float4*)(W_ih + (size_t)(1024 + j) * 1024) + k4;
                const float4* m2 = (const float4*)(W_ih + (size_t)(2048 + j) * 1024) + k4;
                const float4* m3 = (const float4*)(W_hh + (size_t)j * 1024) + k4;
                const float4* m4p = (const float4*)(W_hh + (size_t)(1024 + j) * 1024) + k4;
                const float4* m5 = (const float4*)(W_hh + (size_t)(2048 + j) * 1024) + k4;
                float a0 = 0, a1 = 0, a2 = 0, a3 = 0, a4 = 0, a5 = 0;
#pragma unroll
                for (int i = 0; i < 2; i++) {
                    int k = lane + 32 * i;
                    float4 x = __ldg(xv + k);
                    float4 h = __ldcg(hv + k);
                    float4 m;
                    m = __ldg(m0 + k); a0 = fmaf(m.x, x.x, a0); a0 = fmaf(m.y, x.y, a0); a0 = fmaf(m.z, x.z, a0); a0 = fmaf(m.w, x.w, a0);
                    m = __ldg(m1 + k); a1 = fmaf(m.x, x.x, a1); a1 = fmaf(m.y, x.y, a1); a1 = fmaf(m.z, x.z, a1); a1 = fmaf(m.w, x.w, a1);
                    m = __ldg(m2 + k); a2 = fmaf(m.x, x.x, a2); a2 = fmaf(m.y, x.y, a2); a2 = fmaf(m.z, x.z, a2); a2 = fmaf(m.w, x.w, a2);
                    m = __ldg(m3 + k); a3 = fmaf(m.x, h.x, a3); a3 = fmaf(m.y, h.y, a3); a3 = fmaf(m.z, h.z, a3); a3 = fmaf(m.w, h.w, a3);
                    m = __ldg(m4p + k); a4 = fmaf(m.x, h.x, a4); a4 = fmaf(m.y, h.y, a4); a4 = fmaf(m.z, h.z, a4); a4 = fmaf(m.w, h.w, a4);
                    m = __ldg(m5 + k); a5 = fmaf(m.x, h.x, a5); a5 = fmaf(m.y, h.y, a5); a5 = fmaf(m.z, h.z, a5); a5 = fmaf(m.w, h.w, a5);
                }
                a0 = warp_sum(a0); a1 = warp_sum(a1); a2 = warp_sum(a2);
                a3 = warp_sum(a3); a4 = warp_sum(a4); a5 = warp_sum(a5);
                if (lane == 0) {
                    s_gru[g][sub][0] = a0; s_gru[g][sub][1] = a1; s_gru[g][sub][2] = a2;
                    s_gru[g][sub][3] = a3; s_gru[g][sub][4] = a4; s_gru[g][sub][5] = a5;
                }
            }
            __syncthreads();
            if (tid < 4) {
                int jo = blk * 4 + tid;
                if (jo < 1024) {
                    float D[6];
#pragma unroll
                    for (int d = 0; d < 6; d++)
                        D[d] = s_gru[tid][0][d] + s_gru[tid][1][d] + s_gru[tid][2][d] + s_gru[tid][3][d];
                    float gr = D[0] + __ldg(&b_ih[jo]);
                    float gz = D[1] + __ldg(&b_ih[1024 + jo]);
                    float gn = D[2] + __ldg(&b_ih[2048 + jo]);
                    float hr = D[3] + __ldg(&b_hh[jo]);
                    float hz = D[4] + __ldg(&b_hh[1024 + jo]);
                    float hn = D[5] + __ldg(&b_hh[2048 + jo]);
                    float r = sigmoid_fast(gr + hr);
                    float z = sigmoid_fast(gz + hz);
                    float n = tanh_fast(gn + r * hn);
                    float hold = __ldcg(&g_h[pold][jo]);
                    __stcg(&g_h[pnew][jo], (1.f - z) * n + z * hold);
                }
            }
        }
        gsync(tgt);
        if (blk == 0 && tid == 0) {
            atomicExch(&g_M[par ^ 1], 0u);
            atomicExch(&g_best[par ^ 1], 0ull);
        }

        // ---- q[a] = h_new . Wq[a,:] ----
        {
            int a = w * NBLK + blk;
            if (w < 4 && a < 1024) {
                const float4* mq = (const float4*)(Wq + (size_t)a * 1024);
                const float4* hv = (const float4*)g_h[pnew];
                float acc = 0.f;
#pragma unroll
                for (int i = 0; i < 8; i++) {
                    int k = lane + 32 * i;
                    float4 m = __ldg(mq + k);
                    float4 h = __ldcg(hv + k);
                    acc = fmaf(m.x, h.x, acc); acc = fmaf(m.y, h.y, acc);
                    acc = fmaf(m.z, h.z, acc); acc = fmaf(m.w, h.w, acc);
                }
                acc = warp_sum(acc);
                if (lane == 0) __stcg(&g_q[a], acc);
            }
        }
        gsync(tgt);

        // ---- s[j] = sum_a tanh(eproj[j,a] + q[a]) * v_a[a] ----
        {
            int j = w * NBLK + blk;
            if (w < 7 && j < 2048) {
                const float4* ep = (const float4*)(g_eproj + (size_t)j * 1024);
                const float4* qv = (const float4*)g_q;
                const float4* vv = (const float4*)va;
                float acc = 0.f;
#pragma unroll 4
                for (int i = 0; i < 8; i++) {
                    int k = lane + 32 * i;
                    float4 e4 = __ldg(ep + k);
                    float4 q4 = __ldcg(qv + k);
                    float4 v4 = __ldg(vv + k);
                    acc = fmaf(tanh_fast(e4.x + q4.x), v4.x, acc);
                    acc = fmaf(tanh_fast(e4.y + q4.y), v4.y, acc);
                    acc = fmaf(tanh_fast(e4.z + q4.z), v4.z, acc);
                    acc = fmaf(tanh_fast(e4.w + q4.w), v4.w, acc);
                }
                acc = warp_sum(acc);
                if (lane == 0) __stcg(&g_s[j], acc);
            }
        }
        gsync(tgt);

        // ---- softmax (redundant stats) + ctx partials + weights output ----
        if (blk < 128) {
            float v4[4];
            float lm = -3.4e38f;
#pragma unroll
            for (int r = 0; r < 4; r++) {
                v4[r] = __ldcg(&g_s[tid + 512 * r]);
                lm = fmaxf(lm, v4[r]);
            }
#pragma unroll
            for (int o = 16; o; o >>= 1) lm = fmaxf(lm, __shfl_xor_sync(0xffffffffu, lm, o));
            if (lane == 0) s_red[w] = lm;
            __syncthreads();
            float m = s_red[0];
#pragma unroll
            for (int k = 1; k < 16; k++) m = fmaxf(m, s_red[k]);
            __syncthreads();
            float ls = 0.f;
#pragma unroll
            for (int r = 0; r < 4; r++) ls += expf(v4[r] - m);
            ls = warp_sum(ls);
            if (lane == 0) s_red[w] = ls;
            __syncthreads();
            float tot = s_red[0];
#pragma unroll
            for (int k = 1; k < 16; k++) tot += s_red[k];
            float inv = 1.f / tot;

            if (blk == 0) {
                size_t base = (size_t)NBOUND + (size_t)t * SDIM;
#pragma unroll
                for (int r = 0; r < 4; r++)
                    out[base + tid + 512 * r] = expf(v4[r] - m) * inv;
            }

            int sc = blk >> 4;
            int ac = blk & 15;
            int a0 = ac * 64;
            int g = tid >> 6, al = tid & 63;
            float acc = 0.f;
            int sb = sc * 256 + g * 32;
            for (int ss = 0; ss < 32; ss++) {
                int s = sb + ss;
                float wv = expf(__ldcg(&g_s[s]) - m) * inv;
                acc = fmaf(wv, __ldg(&emb[(size_t)s * 1024 + a0 + al]), acc);
            }
            float* sred = s_As;
            sred[g * 64 + al] = acc;
            __syncthreads();
            if (tid < 64) {
                float c = 0.f;
#pragma unroll
                for (int gg = 0; gg < 8; gg++) c += sred[gg * 64 + tid];
                __stcg(&g_ctx_part[sc][a0 + tid], c);
            }
        }
        gsync(tgt);

        // ---- vocab: bf16 GEMV + bounds (bounds kept in smem) ----
        float* ms = s_As;
        for (int i = tid; i < 1024; i += NTHR) ms[i] = __ldcg(&g_h[pnew][i]);
        for (int i = tid; i < 1024; i += NTHR) {
            float c = 0.f;
#pragma unroll
            for (int p = 0; p < 8; p++) c += __ldcg(&g_ctx_part[p][i]);
            ms[1024 + i] = c;
        }
        __syncthreads();
        const float4* m4 = (const float4*)ms;
        float wmax = -3.4e38f;
        {
            int r = 0;
            for (int v = gw; v < VDIM; v += NWTOT, r++) {
                const unsigned long long* r8 =
                    (const unsigned long long*)(g_wbf + (size_t)v * MERGED);
                float acc = 0.f, ab = 0.f;
#pragma unroll 8
                for (int i = 0; i < 16; i++) {
                    unsigned long long u = __ldcs(r8 + lane + 32 * i);
                    float4 mm = m4[lane + 32 * i];
                    unsigned lo = (unsigned)u, hi = (unsigned)(u >> 32);
                    float2 f0 = __bfloat1622float2(*(__nv_bfloat162*)&lo);
                    float2 f1 = __bfloat1622float2(*(__nv_bfloat162*)&hi);
                    acc = fmaf(f0.x, mm.x, acc); ab = fmaf(fabsf(f0.x), fabsf(mm.x), ab);
                    acc = fmaf(f0.y, mm.y, acc); ab = fmaf(fabsf(f0.y), fabsf(mm.y), ab);
                    acc = fmaf(f1.x, mm.z, acc); ab = fmaf(fabsf(f1.x), fabsf(mm.z), ab);
                    acc = fmaf(f1.y, mm.w, acc); ab = fmaf(fabsf(f1.y), fabsf(mm.w), ab);
                }
                acc = warp_sum(acc);
                ab = warp_sum(ab);
                if (lane == 0) {
                    float A = acc + __ldg(&bout[v]);
                    float B = fmaf(ab, 0.00390625f, 1e-4f);
                    s_ub[w][r] = A + B;
                    wmax = fmaxf(wmax, A - B);
                }
            }
            if (lane == 0) for (; r < 11; r++) s_ub[w][r] = -3.4e38f;
        }
#pragma unroll
        for (int o = 16; o; o >>= 1) wmax = fmaxf(wmax, __shfl_xor_sync(0xffffffffu, wmax, o));
        if (lane == 0) s_red[w] = wmax;
        __syncthreads();
        if (tid == 0) {
            float bm = s_red[0];
#pragma unroll
            for (int k = 1; k < 16; k++) bm = fmaxf(bm, s_red[k]);
            atomicMax(&g_M[par], enc_f(bm));
            s_cnt = 0;
        }
        gsync(tgt);

        // ---- scan own smem bounds + exact fp32 rescore ----
        {
            float thr = dec_f(__ldcg(&g_M[par]));
            if (lane == 0) {
#pragma unroll
                for (int r = 0; r < 11; r++) {
                    if (s_ub[w][r] >= thr) {
                        int p = atomicAdd(&s_cnt, 1);
                        if (p < 32) s_cand[p] = gw + r * NWTOT;
                    }
                }
            }
        }
        __syncthreads();
        int nc = min(s_cnt, 32);
        for (int c = 0; c < nc; c++) {
            int v = s_cand[c];
            float4 rr = __ldg((const float4*)(Wout + (size_t)v * MERGED) + tid);
            float4 mm = m4[tid];
            float a = fmaf(rr.x, mm.x, fmaf(rr.y, mm.y, fmaf(rr.z, mm.z, rr.w * mm.w)));
            a = warp_sum(a);
            if (lane == 0) s_red[w] = a;
            __syncthreads();
            if (tid == 0) {
                float L = 0.f;
#pragma unroll
                for (int k = 0; k < 16; k++) L += s_red[k];
                L += __ldg(&bout[v]);
                unsigned long long pk =
                    ((unsigned long long)enc_f(L) << 32) |
                    (unsigned long long)(0xFFFFFFFFu - (unsigned)v);
                atomicMax(&g_best[par], pk);
            }
            __syncthreads();
        }
        gsync(tgt);

        if (tid == 0) {
            unsigned long long pk = __ldcg(&g_best[par]);
            int wd = (int)(0xFFFFFFFFu - (unsigned)(pk & 0xFFFFFFFFull));
            s_word = wd;
            if (blk == 0) out[t] = (float)wd;
        }
        __syncthreads();
        word = s_word;
    }
}

// ---------------- launch ----------------
extern "C" void kernel_launch(void* const* d_in, const int* in_sizes, int n_in,
                              void* d_out, int out_size) {
    const float* hidden     = (const float*)d_in[0];
    const float* embeddings = (const float*)d_in[1];
    const float* emb_table  = (const float*)d_in[2];
    const float* W_ih       = (const float*)d_in[3];
    const float* W_hh       = (const float*)d_in[4];
    const float* b_ih       = (const float*)d_in[5];
    const float* b_hh       = (const float*)d_in[6];
    const float* W_e        = (const float*)d_in[7];
    const float* W_q        = (const float*)d_in[8];
    const float* b_a        = (const float*)d_in[9];
    const float* v_a        = (const float*)d_in[10];
    const float* W_out      = (const float*)d_in[11];
    const float* b_out      = (const float*)d_in[12];
    float* out = (float*)d_out;

    k_mega<<<NBLK, NTHR>>>(hidden, embeddings, emb_table, W_ih, W_hh, b_ih, b_hh,
                           W_e, W_q, b_a, v_a, W_out, b_out, out);
}

// round 10
// speedup vs baseline: 1.2975x; 1.1448x over previous
#include <cuda_runtime.h>
#include <cuda_bf16.h>
#include <cstdint>

#define HDIM 1024
#define SDIM 2048
#define VDIM 50257
#define NBOUND 25
#define MERGED 2048
#define NBLK 296           // 148 SMs x 2 co-resident blocks
#define NTHR 512
#define NWTOT (NBLK * 16)  // 4736 warps

// ---------------- device scratch ----------------
__device__ __align__(16) float g_h[2][HDIM];
__device__ __align__(16) float g_q[HDIM];
__device__ __align__(16) float g_s[SDIM];
__device__ __align__(16) float g_ctx_part[8][HDIM];
__device__ __align__(16) float g_eproj[(size_t)SDIM * HDIM];          // 8 MB
__device__ __align__(16) unsigned char g_wq[(size_t)VDIM * MERGED];   // 103 MB int8 W_out
__device__ __align__(16) float g_scale[VDIM];                         // per-row scale
__device__ __align__(16) float g_qb[VDIM];                            // per-row ||residual||_2
__device__ unsigned g_M[2];
__device__ unsigned long long g_best[2];
__device__ unsigned g_bar_count, g_bar_phase;

// ---------------- helpers ----------------
__device__ __forceinline__ float warp_sum(float v) {
#pragma unroll
    for (int o = 16; o; o >>= 1) v += __shfl_xor_sync(0xffffffffu, v, o);
    return v;
}
__device__ __forceinline__ float warp_max(float v) {
#pragma unroll
    for (int o = 16; o; o >>= 1) v = fmaxf(v, __shfl_xor_sync(0xffffffffu, v, o));
    return v;
}
__device__ __forceinline__ unsigned enc_f(float f) {
    unsigned b = __float_as_uint(f);
    return (b & 0x80000000u) ? ~b : (b | 0x80000000u);
}
__device__ __forceinline__ float dec_f(unsigned u) {
    unsigned b = (u & 0x80000000u) ? (u ^ 0x80000000u) : ~u;
    return __uint_as_float(b);
}
__device__ __forceinline__ float exp2_fast(float y) {
    y = fminf(fmaxf(y, -60.f), 60.f);
    float n = rintf(y);
    float f = y - n;
    float p = 1.5403530e-4f;
    p = fmaf(p, f, 1.3333558e-3f);
    p = fmaf(p, f, 9.6181291e-3f);
    p = fmaf(p, f, 5.5504109e-2f);
    p = fmaf(p, f, 2.4022651e-1f);
    p = fmaf(p, f, 6.9314718e-1f);
    p = fmaf(p, f, 1.0f);
    return __int_as_float(((int)n + 127) << 23) * p;
}
__device__ __forceinline__ float tanh_fast(float x) {
    float e = exp2_fast(x * 2.885390081777927f);
    return 1.f - 2.f / (e + 1.f);
}
__device__ __forceinline__ float sigmoid_fast(float x) {
    float e = exp2_fast(-1.4426950408889634f * x);
    return 1.f / (1.f + e);
}

// grid-wide barrier
__device__ __forceinline__ void gsync(unsigned& tgt) {
    __syncthreads();
    if (threadIdx.x == 0) {
        __threadfence();
        unsigned v = atomicAdd(&g_bar_count, 1u);
        if (v == NBLK - 1) {
            g_bar_count = 0;
            asm volatile("st.release.gpu.u32 [%0], %1;" :: "l"(&g_bar_phase), "r"(tgt) : "memory");
        } else {
            unsigned p;
            do {
                asm volatile("ld.acquire.gpu.u32 %0, [%1];" : "=r"(p) : "l"(&g_bar_phase) : "memory");
            } while ((int)(p - tgt) < 0);
        }
    }
    __syncthreads();
    tgt++;
}

// accumulate one packed int8 quad against a float4
__device__ __forceinline__ void acc_q(float& a, unsigned u, float4 mm) {
    a = fmaf((float)(int)(signed char)(u      ), mm.x, a);
    a = fmaf((float)(int)(signed char)(u >>  8), mm.y, a);
    a = fmaf((float)(int)(signed char)(u >> 16), mm.z, a);
    a = fmaf((float)(int)(signed char)(u >> 24), mm.w, a);
}

// ---------------- the persistent mega-kernel ----------------
__global__ __launch_bounds__(NTHR, 2) void k_mega(
    const float* __restrict__ hidden, const float* __restrict__ emb,
    const float* __restrict__ emb_table,
    const float* __restrict__ W_ih, const float* __restrict__ W_hh,
    const float* __restrict__ b_ih, const float* __restrict__ b_hh,
    const float* __restrict__ We, const float* __restrict__ Wq,
    const float* __restrict__ ba, const float* __restrict__ va,
    const float* __restrict__ Wout, const float* __restrict__ bout,
    float* __restrict__ out)
{
    __shared__ __align__(16) float s_As[128 * 36];   // eproj A tile; reused as merge vec
    __shared__ __align__(16) float s_Bs[64 * 33];    // eproj B tile
    __shared__ float s_gru[4][4][6];
    __shared__ float s_red[16];
    __shared__ float s_ub[16][11];                   // per-warp row upper bounds
    __shared__ float s_nm;                           // ||m||_2 for this step
    __shared__ int s_cand[32];
    __shared__ int s_cnt;
    __shared__ int s_word;

    const int tid = threadIdx.x;
    const int blk = blockIdx.x;
    const int w = tid >> 5, lane = tid & 31;
    const int gw = blk * 16 + w;

    unsigned tgt = *((volatile unsigned*)&g_bar_phase) + 1;

    // ---------- phase 0a: init + int8 quant of W_out (warp per row) ----------
    if (blk == 0 && tid < 2) { g_M[tid] = 0u; g_best[tid] = 0ull; }
    if (blk == 1) {
        for (int i = tid; i < HDIM; i += NTHR) g_h[0][i] = hidden[i];
    }
    for (int v = gw; v < VDIM; v += NWTOT) {
        const float4* src = (const float4*)(Wout + (size_t)v * MERGED);
        // pass 1: row absmax
        float am = 0.f;
#pragma unroll 4
        for (int i = 0; i < 16; i++) {
            float4 f = __ldg(src + lane + 32 * i);
            am = fmaxf(am, fmaxf(fmaxf(fabsf(f.x), fabsf(f.y)), fmaxf(fabsf(f.z), fabsf(f.w))));
        }
        am = warp_max(am);
        am = fmaxf(am, 1e-20f);
        float scale = am * (1.f / 127.f);
        float inv = 127.f / am;
        // pass 2: quantize (L1 re-read), residual norm
        unsigned* dst = (unsigned*)(g_wq + (size_t)v * MERGED);
        float r2 = 0.f;
#pragma unroll 4
        for (int i = 0; i < 16; i++) {
            float4 f = __ldg(src + lane + 32 * i);
            int q0 = min(127, max(-127, __float2int_rn(f.x * inv)));
            int q1 = min(127, max(-127, __float2int_rn(f.y * inv)));
            int q2 = min(127, max(-127, __float2int_rn(f.z * inv)));
            int q3 = min(127, max(-127, __float2int_rn(f.w * inv)));
            float r0 = f.x - (float)q0 * scale;
            float r1 = f.y - (float)q1 * scale;
            float rr2 = f.z - (float)q2 * scale;
            float r3 = f.w - (float)q3 * scale;
            r2 = fmaf(r0, r0, r2); r2 = fmaf(r1, r1, r2);
            r2 = fmaf(rr2, rr2, r2); r2 = fmaf(r3, r3, r2);
            unsigned pk = (q0 & 0xFF) | ((q1 & 0xFF) << 8) | ((q2 & 0xFF) << 16) | ((unsigned)(q3 & 0xFF) << 24);
            __stcs(dst + lane + 32 * i, pk);
        }
        r2 = warp_sum(r2);
        if (lane == 0) {
            g_scale[v] = scale;
            g_qb[v] = sqrtf(r2);
        }
    }

    // ---------- phase 0b: eproj (blocks 0-255, one 128x64 tile each) ----------
    if (blk < 256) {
        const int ts0 = (blk >> 4) * 128;
        const int ta0 = (blk & 15) * 64;
        const int ts = tid >> 4;
        const int ta = tid & 15;
        float acc[4][4];
#pragma unroll
        for (int i = 0; i < 4; i++)
#pragma unroll
            for (int j = 0; j < 4; j++) acc[i][j] = 0.f;
        __syncthreads();
        for (int kt = 0; kt < 1024; kt += 32) {
#pragma unroll
            for (int r = 0; r < 8; r++) {
                int e0 = tid + NTHR * r;
                int si = e0 >> 5, kk = e0 & 31;
                s_As[si * 36 + kk] = emb[(size_t)(ts0 + si) * 1024 + kt + kk];
            }
#pragma unroll
            for (int r = 0; r < 4; r++) {
                int e0 = tid + NTHR * r;
                int ai = e0 >> 5, kk = e0 & 31;
                s_Bs[ai * 33 + kk] = We[(size_t)(ta0 + ai) * 1024 + kt + kk];
            }
            __syncthreads();
#pragma unroll
            for (int k = 0; k < 32; k++) {
                float a0 = s_As[ts * 36 + k];
                float a1 = s_As[(ts + 32) * 36 + k];
                float a2 = s_As[(ts + 64) * 36 + k];
                float a3 = s_As[(ts + 96) * 36 + k];
                float b0 = s_Bs[(ta * 4 + 0) * 33 + k];
                float b1 = s_Bs[(ta * 4 + 1) * 33 + k];
                float b2 = s_Bs[(ta * 4 + 2) * 33 + k];
                float b3 = s_Bs[(ta * 4 + 3) * 33 + k];
                acc[0][0] = fmaf(a0, b0, acc[0][0]); acc[0][1] = fmaf(a0, b1, acc[0][1]);
                acc[0][2] = fmaf(a0, b2, acc[0][2]); acc[0][3] = fmaf(a0, b3, acc[0][3]);
                acc[1][0] = fmaf(a1, b0, acc[1][0]); acc[1][1] = fmaf(a1, b1, acc[1][1]);
                acc[1][2] = fmaf(a1, b2, acc[1][2]); acc[1][3] = fmaf(a1, b3, acc[1][3]);
                acc[2][0] = fmaf(a2, b0, acc[2][0]); acc[2][1] = fmaf(a2, b1, acc[2][1]);
                acc[2][2] = fmaf(a2, b2, acc[2][2]); acc[2][3] = fmaf(a2, b3, acc[2][3]);
                acc[3][0] = fmaf(a3, b0, acc[3][0]); acc[3][1] = fmaf(a3, b1, acc[3][1]);
                acc[3][2] = fmaf(a3, b2, acc[3][2]); acc[3][3] = fmaf(a3, b3, acc[3][3]);
            }
            __syncthreads();
        }
        float4 bb = __ldg((const float4*)(ba + ta0) + ta);
#pragma unroll
        for (int i = 0; i < 4; i++) {
            float4 o = make_float4(acc[i][0] + bb.x, acc[i][1] + bb.y,
                                   acc[i][2] + bb.z, acc[i][3] + bb.w);
            *(float4*)&g_eproj[(size_t)(ts0 + ts + 32 * i) * 1024 + ta0 + ta * 4] = o;
        }
    }
    gsync(tgt);

    // ---------- decode loop ----------
    int word = 1;  // SOS
    for (int t = 0; t < NBOUND; t++) {
        const int par = t & 1;
        const int pold = par, pnew = par ^ 1;

        // ---- GRU: 16 warps = 4 rows/block x 4 k-slices ----
        {
            int g = w >> 2, sub = w & 3;
            int j = blk * 4 + g;
            if (j < 1024) {
                int k4 = sub * 64;
                const float4* xv = (const float4*)(emb_table + (size_t)word * 1024) + k4;
                const float4* hv = (const float4*)g_h[pold] + k4;
                const float4* m0 = (const float4*)(W_ih + (size_t)j * 1024) + k4;
                const float4* m1 = (const float4*)(W_ih + (size_t)(1024 + j) * 1024) + k4;
                const float4* m2 = (const float4*)(W_ih + (size_t)(2048 + j) * 1024) + k4;
                const float4* m3 = (const float4*)(W_hh + (size_t)j * 1024) + k4;
                const float4* m4p = (const float4*)(W_hh + (size_t)(1024 + j) * 1024) + k4;
                const float4* m5 = (const float4*)(W_hh + (size_t)(2048 + j) * 1024) + k4;
                float a0 = 0, a1 = 0, a2 = 0, a3 = 0, a4 = 0, a5 = 0;
#pragma unroll
                for (int i = 0; i < 2; i++) {
                    int k = lane + 32 * i;
                    float4 x = __ldg(xv + k);
                    float4 h = __ldcg(hv + k);
                    float4 m;
                    m = __ldg(m0 + k); a0 = fmaf(m.x, x.x, a0); a0 = fmaf(m.y, x.y, a0); a0 = fmaf(m.z, x.z, a0); a0 = fmaf(m.w, x.w, a0);
                    m = __ldg(m1 + k); a1 = fmaf(m.x, x.x, a1); a1 = fmaf(m.y, x.y, a1); a1 = fmaf(m.z, x.z, a1); a1 = fmaf(m.w, x.w, a1);
                    m = __ldg(m2 + k); a2 = fmaf(m.x, x.x, a2); a2 = fmaf(m.y, x.y, a2); a2 = fmaf(m.z, x.z, a2); a2 = fmaf(m.w, x.w, a2);
                    m = __ldg(m3 + k); a3 = fmaf(m.x, h.x, a3); a3 = fmaf(m.y, h.y, a3); a3 = fmaf(m.z, h.z, a3); a3 = fmaf(m.w, h.w, a3);
                    m = __ldg(m4p + k); a4 = fmaf(m.x, h.x, a4); a4 = fmaf(m.y, h.y, a4); a4 = fmaf(m.z, h.z, a4); a4 = fmaf(m.w, h.w, a4);
                    m = __ldg(m5 + k); a5 = fmaf(m.x, h.x, a5); a5 = fmaf(m.y, h.y, a5); a5 = fmaf(m.z, h.z, a5); a5 = fmaf(m.w, h.w, a5);
                }
                a0 = warp_sum(a0); a1 = warp_sum(a1); a2 = warp_sum(a2);
                a3 = warp_sum(a3); a4 = warp_sum(a4); a5 = warp_sum(a5);
                if (lane == 0) {
                    s_gru[g][sub][0] = a0; s_gru[g][sub][1] = a1; s_gru[g][sub][2] = a2;
                    s_gru[g][sub][3] = a3; s_gru[g][sub][4] = a4; s_gru[g][sub][5] = a5;
                }
            }
            __syncthreads();
            if (tid < 4) {
                int jo = blk * 4 + tid;
                if (jo < 1024) {
                    float D[6];
#pragma unroll
                    for (int d = 0; d < 6; d++)
                        D[d] = s_gru[tid][0][d] + s_gru[tid][1][d] + s_gru[tid][2][d] + s_gru[tid][3][d];
                    float gr = D[0] + __ldg(&b_ih[jo]);
                    float gz = D[1] + __ldg(&b_ih[1024 + jo]);
                    float gn = D[2] + __ldg(&b_ih[2048 + jo]);
                    float hr = D[3] + __ldg(&b_hh[jo]);
                    float hz = D[4] + __ldg(&b_hh[1024 + jo]);
                    float hn = D[5] + __ldg(&b_hh[2048 + jo]);
                    float r = sigmoid_fast(gr + hr);
                    float z = sigmoid_fast(gz + hz);
                    float n = tanh_fast(gn + r * hn);
                    float hold = __ldcg(&g_h[pold][jo]);
                    __stcg(&g_h[pnew][jo], (1.f - z) * n + z * hold);
                }
            }
        }
        gsync(tgt);
        if (blk == 0 && tid == 0) {
            atomicExch(&g_M[par ^ 1], 0u);
            atomicExch(&g_best[par ^ 1], 0ull);
        }

        // ---- q[a] = h_new . Wq[a,:] ----
        {
            int a = w * NBLK + blk;
            if (w < 4 && a < 1024) {
                const float4* mq = (const float4*)(Wq + (size_t)a * 1024);
                const float4* hv = (const float4*)g_h[pnew];
                float acc = 0.f;
#pragma unroll
                for (int i = 0; i < 8; i++) {
                    int k = lane + 32 * i;
                    float4 m = __ldg(mq + k);
                    float4 h = __ldcg(hv + k);
                    acc = fmaf(m.x, h.x, acc); acc = fmaf(m.y, h.y, acc);
                    acc = fmaf(m.z, h.z, acc); acc = fmaf(m.w, h.w, acc);
                }
                acc = warp_sum(acc);
                if (lane == 0) __stcg(&g_q[a], acc);
            }
        }
        gsync(tgt);

        // ---- s[j] = sum_a tanh(eproj[j,a] + q[a]) * v_a[a] ----
        {
            int j = w * NBLK + blk;
            if (w < 7 && j < 2048) {
                const float4* ep = (const float4*)(g_eproj + (size_t)j * 1024);
                const float4* qv = (const float4*)g_q;
                const float4* vv = (const float4*)va;
                float acc = 0.f;
#pragma unroll 4
                for (int i = 0; i < 8; i++) {
                    int k = lane + 32 * i;
                    float4 e4 = __ldg(ep + k);
                    float4 q4 = __ldcg(qv + k);
                    float4 v4 = __ldg(vv + k);
                    acc = fmaf(tanh_fast(e4.x + q4.x), v4.x, acc);
                    acc = fmaf(tanh_fast(e4.y + q4.y), v4.y, acc);
                    acc = fmaf(tanh_fast(e4.z + q4.z), v4.z, acc);
                    acc = fmaf(tanh_fast(e4.w + q4.w), v4.w, acc);
                }
                acc = warp_sum(acc);
                if (lane == 0) __stcg(&g_s[j], acc);
            }
        }
        gsync(tgt);

        // ---- softmax (redundant stats) + ctx partials + weights output ----
        if (blk < 128) {
            float v4[4];
            float lm = -3.4e38f;
#pragma unroll
            for (int r = 0; r < 4; r++) {
                v4[r] = __ldcg(&g_s[tid + 512 * r]);
                lm = fmaxf(lm, v4[r]);
            }
            lm = warp_max(lm);
            if (lane == 0) s_red[w] = lm;
            __syncthreads();
            float m = s_red[0];
#pragma unroll
            for (int k = 1; k < 16; k++) m = fmaxf(m, s_red[k]);
            __syncthreads();
            float ls = 0.f;
#pragma unroll
            for (int r = 0; r < 4; r++) ls += expf(v4[r] - m);
            ls = warp_sum(ls);
            if (lane == 0) s_red[w] = ls;
            __syncthreads();
            float tot = s_red[0];
#pragma unroll
            for (int k = 1; k < 16; k++) tot += s_red[k];
            float inv = 1.f / tot;

            if (blk == 0) {
                size_t base = (size_t)NBOUND + (size_t)t * SDIM;
#pragma unroll
                for (int r = 0; r < 4; r++)
                    out[base + tid + 512 * r] = expf(v4[r] - m) * inv;
            }

            int sc = blk >> 4;
            int ac = blk & 15;
            int a0 = ac * 64;
            int g = tid >> 6, al = tid & 63;
            float acc = 0.f;
            int sb = sc * 256 + g * 32;
            for (int ss = 0; ss < 32; ss++) {
                int s = sb + ss;
                float wv = expf(__ldcg(&g_s[s]) - m) * inv;
                acc = fmaf(wv, __ldg(&emb[(size_t)s * 1024 + a0 + al]), acc);
            }
            float* sred = s_As;
            sred[g * 64 + al] = acc;
            __syncthreads();
            if (tid < 64) {
                float c = 0.f;
#pragma unroll
                for (int gg = 0; gg < 8; gg++) c += sred[gg * 64 + tid];
                __stcg(&g_ctx_part[sc][a0 + tid], c);
            }
        }
        gsync(tgt);

        // ---- vocab: int8 GEMV + Cauchy-Schwarz bound (bounds in smem) ----
        float* ms = s_As;
        float l2 = 0.f;
        for (int i = tid; i < 1024; i += NTHR) {
            float hv = __ldcg(&g_h[pnew][i]);
            ms[i] = hv;
            l2 = fmaf(hv, hv, l2);
        }
        for (int i = tid; i < 1024; i += NTHR) {
            float c = 0.f;
#pragma unroll
            for (int p = 0; p < 8; p++) c += __ldcg(&g_ctx_part[p][i]);
            ms[1024 + i] = c;
            l2 = fmaf(c, c, l2);
        }
        l2 = warp_sum(l2);
        if (lane == 0) s_red[w] = l2;
        __syncthreads();
        if (tid == 0) {
            float nt = 0.f;
#pragma unroll
            for (int k = 0; k < 16; k++) nt += s_red[k];
            s_nm = sqrtf(nt);
            s_cnt = 0;
        }
        __syncthreads();
        const float4* m4 = (const float4*)ms;
        const float nm = s_nm;
        float wmax = -3.4e38f;
        // 5 row-pairs + 1 single (11 strides)
#pragma unroll
        for (int p = 0; p < 6; p++) {
            int v0 = gw + (2 * p) * NWTOT;
            int v1 = v0 + NWTOT;
            bool ok0 = (v0 < VDIM);
            bool ok1 = (p < 5) && (v1 < VDIM);
            float a0 = 0.f, a1 = 0.f;
            if (ok0) {
                const unsigned* q0 = (const unsigned*)(g_wq + (size_t)v0 * MERGED);
                const unsigned* q1 = (const unsigned*)(g_wq + (size_t)(ok1 ? v1 : v0) * MERGED);
#pragma unroll 8
                for (int i = 0; i < 16; i++) {
                    int idx = lane + 32 * i;
                    unsigned u0 = __ldcs(q0 + idx);
                    unsigned u1 = __ldcs(q1 + idx);
                    float4 mm = m4[idx];
                    acc_q(a0, u0, mm);
                    acc_q(a1, u1, mm);
                }
                a0 = warp_sum(a0);
                a1 = warp_sum(a1);
            }
            if (lane == 0) {
                if (ok0) {
                    float A0 = a0 * __ldg(&g_scale[v0]) + __ldg(&bout[v0]);
                    float B0 = fmaf(__ldg(&g_qb[v0]), nm, 3e-3f);
                    s_ub[w][2 * p] = A0 + B0;
                    wmax = fmaxf(wmax, A0 - B0);
                } else if (2 * p < 11) s_ub[w][2 * p] = -3.4e38f;
                if (ok1) {
                    float A1 = a1 * __ldg(&g_scale[v1]) + __ldg(&bout[v1]);
                    float B1 = fmaf(__ldg(&g_qb[v1]), nm, 3e-3f);
                    s_ub[w][2 * p + 1] = A1 + B1;
                    wmax = fmaxf(wmax, A1 - B1);
                } else if (2 * p + 1 < 11) s_ub[w][2 * p + 1] = -3.4e38f;
            }
        }
        wmax = warp_max(wmax);
        if (lane == 0) s_red[w] = wmax;
        __syncthreads();
        if (tid == 0) {
            float bm = s_red[0];
#pragma unroll
            for (int k = 1; k < 16; k++) bm = fmaxf(bm, s_red[k]);
            atomicMax(&g_M[par], enc_f(bm));
        }
        gsync(tgt);

        // ---- scan own smem bounds + exact fp32 rescore ----
        {
            float thr = dec_f(__ldcg(&g_M[par]));
            if (lane == 0) {
#pragma unroll
                for (int r = 0; r < 11; r++) {
                    if (s_ub[w][r] >= thr) {
                        int p = atomicAdd(&s_cnt, 1);
                        if (p < 32) s_cand[p] = gw + r * NWTOT;
                    }
                }
            }
        }
        __syncthreads();
        int nc = min(s_cnt, 32);
        for (int c = 0; c < nc; c++) {
            int v = s_cand[c];
            float4 rr = __ldg((const float4*)(Wout + (size_t)v * MERGED) + tid);
            float4 mm = m4[tid];
            float a = fmaf(rr.x, mm.x, fmaf(rr.y, mm.y, fmaf(rr.z, mm.z, rr.w * mm.w)));
            a = warp_sum(a);
            if (lane == 0) s_red[w] = a;
            __syncthreads();
            if (tid == 0) {
                float L = 0.f;
#pragma unroll
                for (int k = 0; k < 16; k++) L += s_red[k];
                L += __ldg(&bout[v]);
                unsigned long long pk =
                    ((unsigned long long)enc_f(L) << 32) |
                    (unsigned long long)(0xFFFFFFFFu - (unsigned)v);
                atomicMax(&g_best[par], pk);
            }
            __syncthreads();
        }
        gsync(tgt);

        if (tid == 0) {
            unsigned long long pk = __ldcg(&g_best[par]);
            int wd = (int)(0xFFFFFFFFu - (unsigned)(pk & 0xFFFFFFFFull));
            s_word = wd;
            if (blk == 0) out[t] = (float)wd;
        }
        __syncthreads();
        word = s_word;
    }
}

// ---------------- launch ----------------
extern "C" void kernel_launch(void* const* d_in, const int* in_sizes, int n_in,
                              void* d_out, int out_size) {
    const float* hidden     = (const float*)d_in[0];
    const float* embeddings = (const float*)d_in[1];
    const float* emb_table  = (const float*)d_in[2];
    const float* W_ih       = (const float*)d_in[3];
    const float* W_hh       = (const float*)d_in[4];
    const float* b_ih       = (const float*)d_in[5];
    const float* b_hh       = (const float*)d_in[6];
    const float* W_e        = (const float*)d_in[7];
    const float* W_q        = (const float*)d_in[8];
    const float* b_a        = (const float*)d_in[9];
    const float* v_a        = (const float*)d_in[10];
    const float* W_out      = (const float*)d_in[11];
    const float* b_out      = (const float*)d_in[12];
    float* out = (float*)d_out;

    k_mega<<<NBLK, NTHR>>>(hidden, embeddings, emb_table, W_ih, W_hh, b_ih, b_hh,
                           W_e, W_q, b_a, v_a, W_out, b_out, out);
}